// round 1
// baseline (speedup 1.0000x reference)
#include <cuda_runtime.h>

// Taylor-expansion causal attention, fp32 baseline.
// attn = 1 + s + 0.5*s^2, s = (q k^T)/sqrt(D), causal, o = attn@v / rowsum(attn).
//
// B=2, H=16, L=2048, D=64. Tiles: 64x64 (q x k), full D=64 in one pass.
// 256 threads (16x16), 4x4 register tile per thread for both GEMMs.

#define BM 64
#define BN 64
#define DK 64
#define PAD 4
#define STRIDE (BM + PAD)   // 68 floats

static constexpr int L_CONST = 2048;

__global__ __launch_bounds__(256)
void taylor_attn_kernel(const float* __restrict__ Q,
                        const float* __restrict__ K,
                        const float* __restrict__ V,
                        float* __restrict__ O)
{
    extern __shared__ float sm[];
    float* QsT = sm;                         // [DK][STRIDE]  QsT[d][q]
    float* KsT = QsT + DK * STRIDE;          // [DK][STRIDE]  KsT[d][k]
    float* Vs  = KsT + DK * STRIDE;          // [BN][STRIDE]  Vs[k][d]
    float* SsT = Vs  + BN * STRIDE;          // [BN][STRIDE]  SsT[k][q]

    const int tid = threadIdx.x;
    const int tx  = tid & 15;       // k-col / d-col group
    const int ty  = tid >> 4;       // q-row group
    const int qt  = blockIdx.x;     // q tile index
    const int bh  = blockIdx.y;     // fused batch*head
    const int qbase = qt * BM;
    const size_t head_off = (size_t)bh * L_CONST * DK;

    const float scale = 0.125f;     // D^-0.5 = 64^-0.5

    // ---- load Q tile (scaled), transposed into smem ----
    for (int t = tid; t < BM * 16; t += 256) {
        const int row = t >> 4;
        const int c4  = (t & 15) << 2;
        float4 val = *(const float4*)(Q + head_off + (size_t)(qbase + row) * DK + c4);
        QsT[(c4 + 0) * STRIDE + row] = val.x * scale;
        QsT[(c4 + 1) * STRIDE + row] = val.y * scale;
        QsT[(c4 + 2) * STRIDE + row] = val.z * scale;
        QsT[(c4 + 3) * STRIDE + row] = val.w * scale;
    }

    float acc[4][4] = {};
    float zacc[4]   = {};

    for (int kt = 0; kt <= qt; ++kt) {
        const int kbase = kt * BN;

        // protect Ks/Vs/SsT against overwrite while prev GEMM2 reads them
        __syncthreads();

        // ---- load K (transposed) and V (row-major) tiles ----
        for (int t = tid; t < BN * 16; t += 256) {
            const int row = t >> 4;
            const int c4  = (t & 15) << 2;
            float4 kv = *(const float4*)(K + head_off + (size_t)(kbase + row) * DK + c4);
            KsT[(c4 + 0) * STRIDE + row] = kv.x;
            KsT[(c4 + 1) * STRIDE + row] = kv.y;
            KsT[(c4 + 2) * STRIDE + row] = kv.z;
            KsT[(c4 + 3) * STRIDE + row] = kv.w;
            float4 vv = *(const float4*)(V + head_off + (size_t)(kbase + row) * DK + c4);
            *(float4*)(Vs + row * STRIDE + c4) = vv;
        }
        __syncthreads();

        // ---- GEMM1: s[q][k] = sum_d QsT[d][q] * KsT[d][k] ----
        float s[4][4] = {};
        #pragma unroll 16
        for (int d = 0; d < DK; ++d) {
            const float4 a = *(const float4*)(QsT + d * STRIDE + 4 * ty);
            const float4 b = *(const float4*)(KsT + d * STRIDE + 4 * tx);
            const float av[4] = {a.x, a.y, a.z, a.w};
            const float bv[4] = {b.x, b.y, b.z, b.w};
            #pragma unroll
            for (int i = 0; i < 4; ++i)
                #pragma unroll
                for (int j = 0; j < 4; ++j)
                    s[i][j] = fmaf(av[i], bv[j], s[i][j]);
        }

        // ---- f(s) = 1 + s + 0.5 s^2, causal mask on diagonal tile ----
        const bool diag = (kt == qt);
        #pragma unroll
        for (int i = 0; i < 4; ++i) {
            const int qg = qbase + 4 * ty + i;
            #pragma unroll
            for (int j = 0; j < 4; ++j) {
                const float sv = s[i][j];
                float a = fmaf(fmaf(0.5f, sv, 1.0f), sv, 1.0f);
                if (diag && (kbase + 4 * tx + j) > qg) a = 0.0f;
                s[i][j] = a;
            }
        }

        // ---- z partial: reduce this thread's 4 cols, then across the 16 tx
        // lanes of the half-warp (lanes sharing ty). Every thread ends with
        // the full row-sum for its 4 q rows. ----
        #pragma unroll
        for (int i = 0; i < 4; ++i) {
            float rs = (s[i][0] + s[i][1]) + (s[i][2] + s[i][3]);
            #pragma unroll
            for (int off = 1; off < 16; off <<= 1)
                rs += __shfl_xor_sync(0xffffffffu, rs, off);
            zacc[i] += rs;
        }

        // ---- store S transposed for GEMM2 ----
        #pragma unroll
        for (int j = 0; j < 4; ++j)
            #pragma unroll
            for (int i = 0; i < 4; ++i)
                SsT[(4 * tx + j) * STRIDE + 4 * ty + i] = s[i][j];
        __syncthreads();

        // ---- GEMM2: acc[q][d] += sum_k SsT[k][q] * Vs[k][d] ----
        #pragma unroll 16
        for (int kk = 0; kk < BN; ++kk) {
            const float4 a = *(const float4*)(SsT + kk * STRIDE + 4 * ty);
            const float4 b = *(const float4*)(Vs  + kk * STRIDE + 4 * tx);
            const float av[4] = {a.x, a.y, a.z, a.w};
            const float bv[4] = {b.x, b.y, b.z, b.w};
            #pragma unroll
            for (int i = 0; i < 4; ++i)
                #pragma unroll
                for (int j = 0; j < 4; ++j)
                    acc[i][j] = fmaf(av[i], bv[j], acc[i][j]);
        }
    }

    // ---- epilogue: normalize and store ----
    #pragma unroll
    for (int i = 0; i < 4; ++i) {
        const float inv = 1.0f / (zacc[i] + 1e-6f);
        float4 outv;
        outv.x = acc[i][0] * inv;
        outv.y = acc[i][1] * inv;
        outv.z = acc[i][2] * inv;
        outv.w = acc[i][3] * inv;
        *(float4*)(O + head_off + (size_t)(qbase + 4 * ty + i) * DK + 4 * tx) = outv;
    }
}

extern "C" void kernel_launch(void* const* d_in, const int* in_sizes, int n_in,
                              void* d_out, int out_size) {
    (void)in_sizes; (void)n_in; (void)out_size;
    const float* q = (const float*)d_in[0];
    const float* k = (const float*)d_in[1];
    const float* v = (const float*)d_in[2];
    float* o = (float*)d_out;

    const int smem_bytes = 4 * DK * STRIDE * sizeof(float);  // 69632 B
    static bool configured = false;
    if (!configured) {
        cudaFuncSetAttribute(taylor_attn_kernel,
                             cudaFuncAttributeMaxDynamicSharedMemorySize,
                             smem_bytes);
        configured = true;
    }

    dim3 grid(L_CONST / BM, 2 * 16);   // 32 q-tiles x 32 (B*H)
    taylor_attn_kernel<<<grid, 256, smem_bytes>>>(q, k, v, o);
}

// round 3
// speedup vs baseline: 3.3359x; 3.3359x over previous
#include <cuda_runtime.h>
#include <cstdint>

// Taylor causal attention via warp-level tf32 mma.sync (m16n8k8), sm_103-safe PTX.
// S = (Q/8)K^T ; P = 1+s+0.5s^2 (causal) ; O += P V ; O /= rowsum(P).
// B=2,H=16,L=2048,D=64. CTA: 128 q-rows, 8 warps (16 rows each), k-tiles of 128.

#define L_SEQ 2048
#define DHEAD 64
#define BM 128
#define BN 128
#define QS_STRIDE 68   // Q/K smem row stride (floats): banks 4*grp+c -> conflict-free
#define VS_STRIDE 72   // V smem row stride: banks 8*c+grp -> conflict-free

static __device__ __forceinline__ uint32_t tf32r(float x) {
    uint32_t u; asm("cvt.rna.tf32.f32 %0, %1;" : "=r"(u) : "f"(x)); return u;
}
static __device__ __forceinline__ void mma8(float* d,
        uint32_t a0, uint32_t a1, uint32_t a2, uint32_t a3,
        uint32_t b0, uint32_t b1) {
    asm volatile(
        "mma.sync.aligned.m16n8k8.row.col.f32.tf32.tf32.f32 "
        "{%0,%1,%2,%3}, {%4,%5,%6,%7}, {%8,%9}, {%0,%1,%2,%3};"
        : "+f"(d[0]), "+f"(d[1]), "+f"(d[2]), "+f"(d[3])
        : "r"(a0), "r"(a1), "r"(a2), "r"(a3), "r"(b0), "r"(b1));
}

__global__ void __launch_bounds__(256, 2)
taylor_attn_mma(const float* __restrict__ Q, const float* __restrict__ K,
                const float* __restrict__ V, float* __restrict__ O)
{
    extern __shared__ float smf[];
    float* Qs = smf;                          // [128][68] tf32-rounded, pre-scaled
    float* Ks = Qs + BM * QS_STRIDE;          // [128][68]
    float* Vs = Ks + BN * QS_STRIDE;          // [128][72]

    const int tid  = threadIdx.x;
    const int wid  = tid >> 5;
    const int lane = tid & 31;
    const int grp  = lane >> 2;      // 0..7
    const int c    = lane & 3;       // 0..3
    const int qt   = (int)gridDim.x - 1 - (int)blockIdx.x;   // big tiles first
    const int bh   = blockIdx.y;
    const int qbase = qt * BM;
    const size_t head_off = (size_t)bh * L_SEQ * DHEAD;

    const int wrow  = 16 * wid;            // warp's first q-row (local)
    const int rloc  = wrow + grp;          // this thread's row (local), +8 for upper
    const int rg    = qbase + rloc;        // global q-row

    // ---- load Q once: scale by D^-1/2, round to tf32 ----
    for (int t = tid; t < BM * 16; t += 256) {
        const int row = t >> 4, c4 = (t & 15) << 2;
        float4 v = *(const float4*)(Q + head_off + (size_t)(qbase + row) * DHEAD + c4);
        float* dst = Qs + row * QS_STRIDE + c4;
        dst[0] = __uint_as_float(tf32r(v.x * 0.125f));
        dst[1] = __uint_as_float(tf32r(v.y * 0.125f));
        dst[2] = __uint_as_float(tf32r(v.z * 0.125f));
        dst[3] = __uint_as_float(tf32r(v.w * 0.125f));
    }

    float oacc[8][4];
    #pragma unroll
    for (int t = 0; t < 8; ++t)
        #pragma unroll
        for (int j = 0; j < 4; ++j) oacc[t][j] = 0.0f;
    float zr0 = 0.0f, zr1 = 0.0f;

    const int c2   = c >> 1;
    const int srcA = (lane & 28) | c2;
    const int srcB = srcA + 2;
    const bool odd = (c & 1);

    for (int kt = 0; kt <= qt; ++kt) {
        const int kbase = kt * BN;

        __syncthreads();   // all warps done reading prev K/V (and Q store visible)

        // ---- load K and V tiles (tf32-rounded) ----
        for (int t = tid; t < BN * 16; t += 256) {
            const int row = t >> 4, c4 = (t & 15) << 2;
            float4 kv = *(const float4*)(K + head_off + (size_t)(kbase + row) * DHEAD + c4);
            float* kd = Ks + row * QS_STRIDE + c4;
            kd[0] = __uint_as_float(tf32r(kv.x));
            kd[1] = __uint_as_float(tf32r(kv.y));
            kd[2] = __uint_as_float(tf32r(kv.z));
            kd[3] = __uint_as_float(tf32r(kv.w));
            float4 vv = *(const float4*)(V + head_off + (size_t)(kbase + row) * DHEAD + c4);
            float* vd = Vs + row * VS_STRIDE + c4;
            vd[0] = __uint_as_float(tf32r(vv.x));
            vd[1] = __uint_as_float(tf32r(vv.y));
            vd[2] = __uint_as_float(tf32r(vv.z));
            vd[3] = __uint_as_float(tf32r(vv.w));
        }
        __syncthreads();

        const bool diag = (kt == qt);

        #pragma unroll
        for (int h = 0; h < 2; ++h) {
            // ---- MMA1: S_half (16 x 64 per warp) = Q @ K^T ----
            float sacc[8][4];
            #pragma unroll
            for (int t = 0; t < 8; ++t)
                #pragma unroll
                for (int j = 0; j < 4; ++j) sacc[t][j] = 0.0f;

            #pragma unroll
            for (int d8 = 0; d8 < DHEAD; d8 += 8) {
                const float* qrow = Qs + rloc * QS_STRIDE + d8;
                const uint32_t a0 = __float_as_uint(qrow[c]);
                const uint32_t a1 = __float_as_uint(qrow[8 * QS_STRIDE + c]);
                const uint32_t a2 = __float_as_uint(qrow[c + 4]);
                const uint32_t a3 = __float_as_uint(qrow[8 * QS_STRIDE + c + 4]);
                #pragma unroll
                for (int t = 0; t < 8; ++t) {
                    const float* krow = Ks + (64 * h + 8 * t + grp) * QS_STRIDE + d8;
                    const uint32_t b0 = __float_as_uint(krow[c]);
                    const uint32_t b1 = __float_as_uint(krow[c + 4]);
                    mma8(sacc[t], a0, a1, a2, a3, b0, b1);
                }
            }

            // ---- epilogue on S_half + MMA2 k-steps ----
            #pragma unroll
            for (int t = 0; t < 8; ++t) {
                const int cb = kbase + 64 * h + 8 * t + 2 * c;  // global col of elem 0
                float s0 = sacc[t][0], s1 = sacc[t][1], s2 = sacc[t][2], s3 = sacc[t][3];
                float p0 = fmaf(fmaf(0.5f, s0, 1.0f), s0, 1.0f);
                float p1 = fmaf(fmaf(0.5f, s1, 1.0f), s1, 1.0f);
                float p2 = fmaf(fmaf(0.5f, s2, 1.0f), s2, 1.0f);
                float p3 = fmaf(fmaf(0.5f, s3, 1.0f), s3, 1.0f);
                if (diag) {
                    if (cb     > rg)     p0 = 0.0f;
                    if (cb + 1 > rg)     p1 = 0.0f;
                    if (cb     > rg + 8) p2 = 0.0f;
                    if (cb + 1 > rg + 8) p3 = 0.0f;
                }
                // round P to tf32 once; z uses the rounded values (matches numerator)
                p0 = __uint_as_float(tf32r(p0));
                p1 = __uint_as_float(tf32r(p1));
                p2 = __uint_as_float(tf32r(p2));
                p3 = __uint_as_float(tf32r(p3));
                zr0 += p0 + p1;
                zr1 += p2 + p3;

                // C-frag -> A-frag permutation (cols {2c,2c+1} -> {c, c+4})
                const float t0 = __shfl_sync(0xffffffffu, p0, srcA);
                const float t1 = __shfl_sync(0xffffffffu, p1, srcA);
                const float u0 = __shfl_sync(0xffffffffu, p0, srcB);
                const float u1 = __shfl_sync(0xffffffffu, p1, srcB);
                const float t2 = __shfl_sync(0xffffffffu, p2, srcA);
                const float t3 = __shfl_sync(0xffffffffu, p3, srcA);
                const float u2 = __shfl_sync(0xffffffffu, p2, srcB);
                const float u3 = __shfl_sync(0xffffffffu, p3, srcB);
                const uint32_t a0 = __float_as_uint(odd ? t1 : t0);
                const uint32_t a2 = __float_as_uint(odd ? u1 : u0);
                const uint32_t a1 = __float_as_uint(odd ? t3 : t2);
                const uint32_t a3 = __float_as_uint(odd ? u3 : u2);

                // MMA2: O(16x64) += P[:, k-step] @ V[k-step, :]
                const float* vbase = Vs + (64 * h + 8 * t + c) * VS_STRIDE + grp;
                #pragma unroll
                for (int tn = 0; tn < 8; ++tn) {
                    const uint32_t b0 = __float_as_uint(vbase[8 * tn]);
                    const uint32_t b1 = __float_as_uint(vbase[4 * VS_STRIDE + 8 * tn]);
                    mma8(oacc[tn], a0, a1, a2, a3, b0, b1);
                }
            }
        }
    }

    // ---- z reduce across the 4 lanes of each row-group ----
    zr0 += __shfl_xor_sync(0xffffffffu, zr0, 1);
    zr0 += __shfl_xor_sync(0xffffffffu, zr0, 2);
    zr1 += __shfl_xor_sync(0xffffffffu, zr1, 1);
    zr1 += __shfl_xor_sync(0xffffffffu, zr1, 2);
    const float inv0 = 1.0f / (zr0 + 1e-6f);
    const float inv1 = 1.0f / (zr1 + 1e-6f);

    // ---- store O: row rg (oacc[t][0..1]) and rg+8 (oacc[t][2..3]) ----
    {
        float* ob0 = O + head_off + (size_t)rg * DHEAD + 2 * c;
        float* ob1 = O + head_off + (size_t)(rg + 8) * DHEAD + 2 * c;
        #pragma unroll
        for (int tn = 0; tn < 8; ++tn) {
            float2 w0; w0.x = oacc[tn][0] * inv0; w0.y = oacc[tn][1] * inv0;
            float2 w1; w1.x = oacc[tn][2] * inv1; w1.y = oacc[tn][3] * inv1;
            *(float2*)(ob0 + 8 * tn) = w0;
            *(float2*)(ob1 + 8 * tn) = w1;
        }
    }
}

extern "C" void kernel_launch(void* const* d_in, const int* in_sizes, int n_in,
                              void* d_out, int out_size) {
    (void)in_sizes; (void)n_in; (void)out_size;
    const float* q = (const float*)d_in[0];
    const float* k = (const float*)d_in[1];
    const float* v = (const float*)d_in[2];
    float* o = (float*)d_out;

    const int smem_bytes = (BM * QS_STRIDE + BN * QS_STRIDE + BN * VS_STRIDE) * 4; // 106496
    static bool configured = false;
    if (!configured) {
        cudaFuncSetAttribute(taylor_attn_mma,
                             cudaFuncAttributeMaxDynamicSharedMemorySize, smem_bytes);
        configured = true;
    }

    dim3 grid(L_SEQ / BM, 2 * 16);   // 16 q-tiles x 32 (B*H)
    taylor_attn_mma<<<grid, 256, smem_bytes>>>(q, k, v, o);
}

// round 4
// speedup vs baseline: 3.5187x; 1.0548x over previous
#include <cuda_runtime.h>
#include <cstdint>

// Taylor causal attention, tf32 mma.sync (m16n8k8), shuffle-free P->MMA2 path.
// S = (Q/8)K^T ; P = 1+s+0.5s^2 (causal) ; O += P V ; O /= rowsum(P).
// B=2,H=16,L=2048,D=64. CTA: 128 q-rows, 8 warps, k-tiles of 128.
//
// Layout tricks:
//  - Q/K smem columns interleaved per 8-block ([s0,s4,s1,s5,s2,s6,s3,s7]) so
//    fragment slot pairs (c, c+4) are physically adjacent -> LDS.64.
//  - MMA2 contracts k in permuted order [0,2,4,6,1,3,5,7]: the needed P
//    A-fragment equals the MMA1 C-fragment in-lane (no shuffles); V supplies
//    rows 2c,2c+1, adjacent in a transposed Vt[d][k] tile -> LDS.64.

#define L_SEQ 2048
#define DHEAD 64
#define BM 128
#define BN 128
#define QS 72    // Q/K smem row stride (floats): read bank-pairs 4g+c, degree 2
#define VT 136   // Vt row stride (floats): same degree-2 property

static __device__ __forceinline__ uint32_t tf32r(float x) {
    uint32_t u; asm("cvt.rna.tf32.f32 %0, %1;" : "=r"(u) : "f"(x)); return u;
}
static __device__ __forceinline__ float tf32f(float x) {
    return __uint_as_float(tf32r(x));
}
static __device__ __forceinline__ void mma8(float* d,
        float a0, float a1, float a2, float a3, float b0, float b1) {
    asm volatile(
        "mma.sync.aligned.m16n8k8.row.col.f32.tf32.tf32.f32 "
        "{%0,%1,%2,%3}, {%4,%5,%6,%7}, {%8,%9}, {%0,%1,%2,%3};"
        : "+f"(d[0]), "+f"(d[1]), "+f"(d[2]), "+f"(d[3])
        : "r"(__float_as_uint(a0)), "r"(__float_as_uint(a1)),
          "r"(__float_as_uint(a2)), "r"(__float_as_uint(a3)),
          "r"(__float_as_uint(b0)), "r"(__float_as_uint(b1)));
}

__global__ void __launch_bounds__(256, 2)
taylor_attn_mma2(const float* __restrict__ Q, const float* __restrict__ K,
                 const float* __restrict__ V, float* __restrict__ O)
{
    extern __shared__ float smf[];
    float* Qs = smf;                 // [128][72] interleaved cols, scaled tf32
    float* Ks = Qs + BM * QS;        // [128][72] interleaved cols
    float* Vt = Ks + BN * QS;        // [64][136] transposed V (Vt[d][k])

    const int tid  = threadIdx.x;
    const int wid  = tid >> 5;
    const int lane = tid & 31;
    const int grp  = lane >> 2;      // 0..7
    const int c    = lane & 3;       // 0..3
    const int qt   = (int)gridDim.x - 1 - (int)blockIdx.x;   // big tiles first
    const int bh   = blockIdx.y;
    const int qbase = qt * BM;
    const size_t head_off = (size_t)bh * L_SEQ * DHEAD;

    const int rloc = 16 * wid + grp;       // thread's q-row (local); +8 = second
    const int rg   = qbase + rloc;

    // ---- load Q once: scale, tf32-round, interleaved-column store ----
    for (int t = tid; t < BM * 16; t += 256) {
        const int row = t >> 4, c4 = (t & 15) << 2;
        float4 v = *(const float4*)(Q + head_off + (size_t)(qbase + row) * DHEAD + c4);
        float* dst = Qs + row * QS + (c4 & ~7) + ((c4 >> 2) & 1);
        dst[0] = tf32f(v.x * 0.125f);
        dst[2] = tf32f(v.y * 0.125f);
        dst[4] = tf32f(v.z * 0.125f);
        dst[6] = tf32f(v.w * 0.125f);
    }

    float oacc[8][4];
    #pragma unroll
    for (int t = 0; t < 8; ++t)
        #pragma unroll
        for (int j = 0; j < 4; ++j) oacc[t][j] = 0.0f;
    float zr0 = 0.0f, zr1 = 0.0f;

    const int vdcol = tid & 63;            // for V transpose staging
    const int vk4   = (tid >> 6) << 2;

    for (int kt = 0; kt <= qt; ++kt) {
        const int kbase = kt * BN;

        __syncthreads();   // previous-iteration readers done with Ks/Vt

        // ---- K tile: tf32-round, interleaved-column store ----
        #pragma unroll 2
        for (int t = tid; t < BN * 16; t += 256) {
            const int row = t >> 4, c4 = (t & 15) << 2;
            float4 kv = *(const float4*)(K + head_off + (size_t)(kbase + row) * DHEAD + c4);
            float* kd = Ks + row * QS + (c4 & ~7) + ((c4 >> 2) & 1);
            kd[0] = tf32f(kv.x);
            kd[2] = tf32f(kv.y);
            kd[4] = tf32f(kv.z);
            kd[6] = tf32f(kv.w);
        }
        // ---- V tile: transpose into Vt[d][k] (coalesced LDG, STS.128) ----
        #pragma unroll
        for (int p = 0; p < 8; ++p) {
            const int kk = p * 16 + vk4;
            const float* vsrc = V + head_off + (size_t)(kbase + kk) * DHEAD + vdcol;
            float4 w;
            w.x = tf32f(vsrc[0]);
            w.y = tf32f(vsrc[DHEAD]);
            w.z = tf32f(vsrc[2 * DHEAD]);
            w.w = tf32f(vsrc[3 * DHEAD]);
            *(float4*)(Vt + vdcol * VT + kk) = w;
        }
        __syncthreads();

        const bool diag = (kt == qt);

        #pragma unroll
        for (int h = 0; h < 2; ++h) {
            // ---- MMA1: S_half (16 x 64 per warp) = Q @ K^T ----
            float sacc[8][4];
            #pragma unroll
            for (int t = 0; t < 8; ++t)
                #pragma unroll
                for (int j = 0; j < 4; ++j) sacc[t][j] = 0.0f;

            #pragma unroll
            for (int d8 = 0; d8 < 8; ++d8) {
                const float2 qa = *(const float2*)(Qs + rloc * QS + 8 * d8 + 2 * c);
                const float2 qb = *(const float2*)(Qs + (rloc + 8) * QS + 8 * d8 + 2 * c);
                #pragma unroll
                for (int t = 0; t < 8; ++t) {
                    const float2 kb = *(const float2*)
                        (Ks + (64 * h + 8 * t + grp) * QS + 8 * d8 + 2 * c);
                    mma8(sacc[t], qa.x, qb.x, qa.y, qb.y, kb.x, kb.y);
                }
            }

            // ---- epilogue + MMA2 k-steps (shuffle-free) ----
            #pragma unroll
            for (int t = 0; t < 8; ++t) {
                const int cb = kbase + 64 * h + 8 * t + 2 * c;   // col of p0/p2
                float s0 = sacc[t][0], s1 = sacc[t][1], s2 = sacc[t][2], s3 = sacc[t][3];
                float p0 = fmaf(fmaf(0.5f, s0, 1.0f), s0, 1.0f);
                float p1 = fmaf(fmaf(0.5f, s1, 1.0f), s1, 1.0f);
                float p2 = fmaf(fmaf(0.5f, s2, 1.0f), s2, 1.0f);
                float p3 = fmaf(fmaf(0.5f, s3, 1.0f), s3, 1.0f);
                if (diag) {
                    if (cb     > rg)     p0 = 0.0f;
                    if (cb + 1 > rg)     p1 = 0.0f;
                    if (cb     > rg + 8) p2 = 0.0f;
                    if (cb + 1 > rg + 8) p3 = 0.0f;
                }
                p0 = tf32f(p0); p1 = tf32f(p1); p2 = tf32f(p2); p3 = tf32f(p3);
                zr0 += p0 + p1;
                zr1 += p2 + p3;

                // A-frag (k-order [0,2,4,6,1,3,5,7]) = C-frag in-lane:
                //   a0=P[g][2c], a1=P[g+8][2c], a2=P[g][2c+1], a3=P[g+8][2c+1]
                // B-frag: V rows kb2+2c, kb2+2c+1 -> adjacent in Vt.
                const int kb2 = 64 * h + 8 * t;
                #pragma unroll
                for (int tn = 0; tn < 8; ++tn) {
                    const float2 vb = *(const float2*)
                        (Vt + (8 * tn + grp) * VT + kb2 + 2 * c);
                    mma8(oacc[tn], p0, p2, p1, p3, vb.x, vb.y);
                }
            }
        }
    }

    // ---- z reduce across the 4 lanes of each row-group ----
    zr0 += __shfl_xor_sync(0xffffffffu, zr0, 1);
    zr0 += __shfl_xor_sync(0xffffffffu, zr0, 2);
    zr1 += __shfl_xor_sync(0xffffffffu, zr1, 1);
    zr1 += __shfl_xor_sync(0xffffffffu, zr1, 2);
    const float inv0 = 1.0f / (zr0 + 1e-6f);
    const float inv1 = 1.0f / (zr1 + 1e-6f);

    // ---- store O: rows rg (regs 0,1) and rg+8 (regs 2,3) ----
    {
        float* ob0 = O + head_off + (size_t)rg * DHEAD + 2 * c;
        float* ob1 = O + head_off + (size_t)(rg + 8) * DHEAD + 2 * c;
        #pragma unroll
        for (int tn = 0; tn < 8; ++tn) {
            float2 w0; w0.x = oacc[tn][0] * inv0; w0.y = oacc[tn][1] * inv0;
            float2 w1; w1.x = oacc[tn][2] * inv1; w1.y = oacc[tn][3] * inv1;
            *(float2*)(ob0 + 8 * tn) = w0;
            *(float2*)(ob1 + 8 * tn) = w1;
        }
    }
}

extern "C" void kernel_launch(void* const* d_in, const int* in_sizes, int n_in,
                              void* d_out, int out_size) {
    (void)in_sizes; (void)n_in; (void)out_size;
    const float* q = (const float*)d_in[0];
    const float* k = (const float*)d_in[1];
    const float* v = (const float*)d_in[2];
    float* o = (float*)d_out;

    const int smem_bytes = (BM * QS + BN * QS + DHEAD * VT) * 4;   // 108544 B
    static bool configured = false;
    if (!configured) {
        cudaFuncSetAttribute(taylor_attn_mma2,
                             cudaFuncAttributeMaxDynamicSharedMemorySize, smem_bytes);
        configured = true;
    }

    dim3 grid(L_SEQ / BM, 2 * 16);   // 16 q-tiles x 32 (B*H)
    taylor_attn_mma2<<<grid, 256, smem_bytes>>>(q, k, v, o);
}

// round 5
// speedup vs baseline: 4.0619x; 1.1544x over previous
#include <cuda_runtime.h>
#include <cstdint>

// Taylor causal attention, tf32 mma.sync, cp.async double-buffered pipeline.
// Preprocessing kernels write tf32-rounded / permuted copies of Q,K,V into
// __device__ scratch so the mainloop is pure cp.async + LDS + MMA + ALU.
// B=2,H=16,L=2048,D=64. CTA: 128 q-rows, 8 warps, k-tiles of 64 (double buf).

#define L_SEQ 2048
#define DHEAD 64
#define NBH   32
#define BM    128
#define BN    64
#define QS    72     // smem row stride (floats) for Qs/Kb/Vb

// preprocessed copies (module-static device memory; no runtime allocation)
__device__ float g_Qp[NBH * L_SEQ * DHEAD];   // scaled+rounded, col-interleaved
__device__ float g_Kp[NBH * L_SEQ * DHEAD];   // rounded, col-interleaved
__device__ float g_Vt[NBH * DHEAD * L_SEQ];   // rounded, transposed [d][k]

static __device__ __forceinline__ uint32_t tf32r(float x) {
    uint32_t u; asm("cvt.rna.tf32.f32 %0, %1;" : "=r"(u) : "f"(x)); return u;
}
static __device__ __forceinline__ float tf32f(float x) {
    return __uint_as_float(tf32r(x));
}
static __device__ __forceinline__ uint32_t smem_u32(const void* p) {
    uint32_t a;
    asm("{ .reg .u64 t; cvta.to.shared.u64 t, %1; cvt.u32.u64 %0, t; }" : "=r"(a) : "l"(p));
    return a;
}
static __device__ __forceinline__ void cp16(uint32_t s, const float* g) {
    asm volatile("cp.async.cg.shared.global [%0], [%1], 16;"
                 :: "r"(s), "l"(__cvta_generic_to_global(g)));
}
static __device__ __forceinline__ void cp_commit() {
    asm volatile("cp.async.commit_group;" ::: "memory");
}
static __device__ __forceinline__ void cp_wait1() {
    asm volatile("cp.async.wait_group 1;" ::: "memory");
}
static __device__ __forceinline__ void cp_wait0() {
    asm volatile("cp.async.wait_group 0;" ::: "memory");
}
static __device__ __forceinline__ void mma8(float* d,
        float a0, float a1, float a2, float a3, float b0, float b1) {
    asm volatile(
        "mma.sync.aligned.m16n8k8.row.col.f32.tf32.tf32.f32 "
        "{%0,%1,%2,%3}, {%4,%5,%6,%7}, {%8,%9}, {%0,%1,%2,%3};"
        : "+f"(d[0]), "+f"(d[1]), "+f"(d[2]), "+f"(d[3])
        : "r"(__float_as_uint(a0)), "r"(__float_as_uint(a1)),
          "r"(__float_as_uint(a2)), "r"(__float_as_uint(a3)),
          "r"(__float_as_uint(b0)), "r"(__float_as_uint(b1)));
}

// ---- prep 1: Q,K -> rounded, column-interleaved (logical j<4 -> phys 2j;
//      logical j+4 -> phys 2j+1, per 8-col block). Q also pre-scaled. ----
__global__ void __launch_bounds__(256)
prep_qk(const float* __restrict__ Q, const float* __restrict__ K)
{
    const int g = blockIdx.x * 256 + threadIdx.x;   // one float4 per tensor
    const int row = g >> 4;
    const int c4  = (g & 15) << 2;
    const int pbase = (c4 & ~7) + ((c4 >> 2) & 1);
    const size_t off = (size_t)row * DHEAD;

    float4 qv = *(const float4*)(Q + off + c4);
    float* qd = g_Qp + off + pbase;
    qd[0] = tf32f(qv.x * 0.125f);
    qd[2] = tf32f(qv.y * 0.125f);
    qd[4] = tf32f(qv.z * 0.125f);
    qd[6] = tf32f(qv.w * 0.125f);

    float4 kv = *(const float4*)(K + off + c4);
    float* kd = g_Kp + off + pbase;
    kd[0] = tf32f(kv.x);
    kd[2] = tf32f(kv.y);
    kd[4] = tf32f(kv.z);
    kd[6] = tf32f(kv.w);
}

// ---- prep 2: V -> rounded, per-head transpose [k][d] -> [d][k] ----
__global__ void __launch_bounds__(256)
prep_vt(const float* __restrict__ V)
{
    __shared__ float ts[32][33];
    const int tx = threadIdx.x & 31, ty = threadIdx.x >> 5;   // 32 x 8
    const int kt0 = (blockIdx.x & 63) * 32;                   // k tile (64 tiles)
    const int dt0 = (blockIdx.x >> 6) * 32;                   // d tile (2 tiles)
    const int bh  = blockIdx.y;
    const float* vsrc = V + (size_t)bh * L_SEQ * DHEAD;
    float* vdst = g_Vt + (size_t)bh * DHEAD * L_SEQ;

    #pragma unroll
    for (int i = 0; i < 4; ++i) {
        const int r = ty + 8 * i;
        ts[r][tx] = vsrc[(size_t)(kt0 + r) * DHEAD + dt0 + tx];
    }
    __syncthreads();
    #pragma unroll
    for (int i = 0; i < 4; ++i) {
        const int r = ty + 8 * i;
        vdst[(size_t)(dt0 + r) * L_SEQ + kt0 + tx] = tf32f(ts[tx][r]);
    }
}

// ---- main kernel ----
__global__ void __launch_bounds__(256, 2)
taylor_attn_pipe(float* __restrict__ O)
{
    extern __shared__ float smf[];
    float* Qs = smf;                       // [128][72]
    float* Kb = Qs + BM * QS;              // [2][64][72]
    float* Vb = Kb + 2 * BN * QS;          // [2][64][72]
    const uint32_t sQs = smem_u32(Qs);
    const uint32_t sKb = smem_u32(Kb);
    const uint32_t sVb = smem_u32(Vb);

    const int tid  = threadIdx.x;
    const int wid  = tid >> 5;
    const int lane = tid & 31;
    const int grp  = lane >> 2;
    const int c    = lane & 3;
    const int qt   = (int)gridDim.x - 1 - (int)blockIdx.x;   // big tiles first
    const int bh   = blockIdx.y;
    const int qbase = qt * BM;
    const size_t head_off = (size_t)bh * L_SEQ * DHEAD;

    const int rloc = 16 * wid + grp;
    const int rg   = qbase + rloc;
    const int jmax = 2 * qt + 1;

    const float* Qg = g_Qp + head_off;
    const float* Kg = g_Kp + head_off;
    const float* Vg = g_Vt + head_off;

    // ---- prologue group: Q tile + K/V tile 0 via cp.async ----
    #pragma unroll
    for (int i = 0; i < 8; ++i) {                 // Q: 2048 chunks / 256 thr
        const int idx = tid + 256 * i;
        const int row = idx >> 4, c16 = (idx & 15) << 2;
        cp16(sQs + (uint32_t)(row * QS + c16) * 4,
             Qg + (size_t)(qbase + row) * DHEAD + c16);
    }
    {
        #pragma unroll
        for (int i = 0; i < 4; ++i) {             // K tile 0: 1024 chunks
            const int idx = tid + 256 * i;
            const int row = idx >> 4, c16 = (idx & 15) << 2;
            cp16(sKb + (uint32_t)(row * QS + c16) * 4,
                 Kg + (size_t)row * DHEAD + c16);
            cp16(sVb + (uint32_t)(row * QS + c16) * 4,
                 Vg + (size_t)row * L_SEQ + c16);
        }
    }
    cp_commit();

    float oacc[8][4];
    #pragma unroll
    for (int t = 0; t < 8; ++t)
        #pragma unroll
        for (int j = 0; j < 4; ++j) oacc[t][j] = 0.0f;
    float zr0 = 0.0f, zr1 = 0.0f;

    for (int j = 0; j <= jmax; ++j) {
        const int buf = j & 1;

        // prefetch tile j+1 into other buffer
        if (j < jmax) {
            const int nb = buf ^ 1;
            const int kb1 = (j + 1) * BN;
            const uint32_t dK = sKb + (uint32_t)(nb * BN * QS) * 4;
            const uint32_t dV = sVb + (uint32_t)(nb * BN * QS) * 4;
            #pragma unroll
            for (int i = 0; i < 4; ++i) {
                const int idx = tid + 256 * i;
                const int row = idx >> 4, c16 = (idx & 15) << 2;
                cp16(dK + (uint32_t)(row * QS + c16) * 4,
                     Kg + (size_t)(kb1 + row) * DHEAD + c16);
                cp16(dV + (uint32_t)(row * QS + c16) * 4,
                     Vg + (size_t)row * L_SEQ + kb1 + c16);
            }
            cp_commit();
            cp_wait1();
        } else {
            cp_wait0();
        }
        __syncthreads();   // tile j visible to all warps

        const float* Kt = Kb + buf * BN * QS;
        const float* Vtb = Vb + buf * BN * QS;
        const int kbase = j * BN;
        const bool diag = (j >= 2 * qt);

        // ---- MMA1: S (16 x 64 per warp) = Q @ K^T ----
        float sacc[8][4];
        #pragma unroll
        for (int t = 0; t < 8; ++t)
            #pragma unroll
            for (int jj = 0; jj < 4; ++jj) sacc[t][jj] = 0.0f;

        #pragma unroll
        for (int d8 = 0; d8 < 8; ++d8) {
            const float2 qa = *(const float2*)(Qs + rloc * QS + 8 * d8 + 2 * c);
            const float2 qb = *(const float2*)(Qs + (rloc + 8) * QS + 8 * d8 + 2 * c);
            #pragma unroll
            for (int t = 0; t < 8; ++t) {
                const float2 kf = *(const float2*)(Kt + (8 * t + grp) * QS + 8 * d8 + 2 * c);
                mma8(sacc[t], qa.x, qb.x, qa.y, qb.y, kf.x, kf.y);
            }
        }

        // ---- epilogue + MMA2 (shuffle-free; P truncates to tf32 in HW) ----
        #pragma unroll
        for (int t = 0; t < 8; ++t) {
            const int cb = kbase + 8 * t + 2 * c;
            float s0 = sacc[t][0], s1 = sacc[t][1], s2 = sacc[t][2], s3 = sacc[t][3];
            float p0 = fmaf(fmaf(0.5f, s0, 1.0f), s0, 1.0f);
            float p1 = fmaf(fmaf(0.5f, s1, 1.0f), s1, 1.0f);
            float p2 = fmaf(fmaf(0.5f, s2, 1.0f), s2, 1.0f);
            float p3 = fmaf(fmaf(0.5f, s3, 1.0f), s3, 1.0f);
            if (diag) {
                if (cb     > rg)     p0 = 0.0f;
                if (cb + 1 > rg)     p1 = 0.0f;
                if (cb     > rg + 8) p2 = 0.0f;
                if (cb + 1 > rg + 8) p3 = 0.0f;
            }
            zr0 += p0 + p1;
            zr1 += p2 + p3;

            // A-frag (k-order [0,2,4,6,1,3,5,7]) is the C-frag in-lane.
            const int kb2 = 8 * t;
            #pragma unroll
            for (int tn = 0; tn < 8; ++tn) {
                const float2 vf = *(const float2*)(Vtb + (8 * tn + grp) * QS + kb2 + 2 * c);
                mma8(oacc[tn], p0, p2, p1, p3, vf.x, vf.y);
            }
        }
        __syncthreads();   // all warps done with buf before it is refilled
    }

    // ---- z reduce across the 4 lanes of each row-group ----
    zr0 += __shfl_xor_sync(0xffffffffu, zr0, 1);
    zr0 += __shfl_xor_sync(0xffffffffu, zr0, 2);
    zr1 += __shfl_xor_sync(0xffffffffu, zr1, 1);
    zr1 += __shfl_xor_sync(0xffffffffu, zr1, 2);
    const float inv0 = 1.0f / (zr0 + 1e-6f);
    const float inv1 = 1.0f / (zr1 + 1e-6f);

    float* ob0 = O + head_off + (size_t)rg * DHEAD + 2 * c;
    float* ob1 = O + head_off + (size_t)(rg + 8) * DHEAD + 2 * c;
    #pragma unroll
    for (int tn = 0; tn < 8; ++tn) {
        float2 w0; w0.x = oacc[tn][0] * inv0; w0.y = oacc[tn][1] * inv0;
        float2 w1; w1.x = oacc[tn][2] * inv1; w1.y = oacc[tn][3] * inv1;
        *(float2*)(ob0 + 8 * tn) = w0;
        *(float2*)(ob1 + 8 * tn) = w1;
    }
}

extern "C" void kernel_launch(void* const* d_in, const int* in_sizes, int n_in,
                              void* d_out, int out_size) {
    (void)in_sizes; (void)n_in; (void)out_size;
    const float* q = (const float*)d_in[0];
    const float* k = (const float*)d_in[1];
    const float* v = (const float*)d_in[2];
    float* o = (float*)d_out;

    const int smem_bytes = (BM * QS + 4 * BN * QS) * 4;   // 110592 B
    static bool configured = false;
    if (!configured) {
        cudaFuncSetAttribute(taylor_attn_pipe,
                             cudaFuncAttributeMaxDynamicSharedMemorySize, smem_bytes);
        configured = true;
    }

    prep_qk<<<(NBH * L_SEQ * DHEAD) / (4 * 256), 256>>>(q, k);
    prep_vt<<<dim3(128, NBH), 256>>>(v);

    dim3 grid(L_SEQ / BM, NBH);   // 16 q-tiles x 32 (B*H)
    taylor_attn_pipe<<<grid, 256, smem_bytes>>>(o);
}

// round 7
// speedup vs baseline: 4.9611x; 1.2214x over previous
#include <cuda_runtime.h>
#include <cuda_fp16.h>
#include <cstdint>

// Taylor causal attention, fp16 mma.sync m16n8k16 (fp32 accum), cp.async
// double-buffered. fp16 mantissa (10b) == tf32 mantissa, so precision matches
// the tf32 version while doubling FLOP/instr and halving smem traffic.
// B=2,H=16,L=2048,D=64. CTA: 128 q-rows, 8 warps, k-tiles of 128.
//
// Layout: columns interleaved per 16-block as [0,1,8,9, 2,3,10,11, ...] so an
// m16n8k16 A/B fragment (logical cols 2c,2c+1,2c+8,2c+9) is one LDS.64.
// MMA2's A-fragment for k-block u equals MMA1's C-fragments of tiles 2u,2u+1
// in-lane (packed to half2) -> no shuffles anywhere.

#define L_SEQ 2048
#define DHEAD 64
#define NBH   32
#define BM    128
#define BN    128
#define QS    72     // Q/K smem row stride in halves (144B; deg-2 banks)
#define VTS   136    // Vt smem row stride in halves (272B; deg-2 banks)

__device__ __align__(16) __half g_Qh[NBH * L_SEQ * DHEAD];  // scaled, interleaved
__device__ __align__(16) __half g_Kh[NBH * L_SEQ * DHEAD];  // interleaved
__device__ __align__(16) __half g_Vth[NBH * DHEAD * L_SEQ]; // [d][k], k-interleaved

static __device__ __forceinline__ uint32_t packh2(float lo, float hi) {
    __half2 h = __floats2half2_rn(lo, hi);
    return *(uint32_t*)&h;
}
static __device__ __forceinline__ uint32_t smem_u32(const void* p) {
    uint32_t a;
    asm("{ .reg .u64 t; cvta.to.shared.u64 t, %1; cvt.u32.u64 %0, t; }" : "=r"(a) : "l"(p));
    return a;
}
static __device__ __forceinline__ void cp16(uint32_t s, const void* g) {
    asm volatile("cp.async.cg.shared.global [%0], [%1], 16;"
                 :: "r"(s), "l"(__cvta_generic_to_global(g)));
}
static __device__ __forceinline__ void cp_commit() {
    asm volatile("cp.async.commit_group;" ::: "memory");
}
static __device__ __forceinline__ void cp_wait1() {
    asm volatile("cp.async.wait_group 1;" ::: "memory");
}
static __device__ __forceinline__ void cp_wait0() {
    asm volatile("cp.async.wait_group 0;" ::: "memory");
}
static __device__ __forceinline__ void mma16(float* d,
        uint32_t a0, uint32_t a1, uint32_t a2, uint32_t a3,
        uint32_t b0, uint32_t b1) {
    asm volatile(
        "mma.sync.aligned.m16n8k16.row.col.f32.f16.f16.f32 "
        "{%0,%1,%2,%3}, {%4,%5,%6,%7}, {%8,%9}, {%0,%1,%2,%3};"
        : "+f"(d[0]), "+f"(d[1]), "+f"(d[2]), "+f"(d[3])
        : "r"(a0), "r"(a1), "r"(a2), "r"(a3), "r"(b0), "r"(b1));
}

// ---- prep 1: Q,K -> fp16, interleaved per 16-col block (Q pre-scaled) ----
__global__ void __launch_bounds__(256)
prep_qk(const float* __restrict__ Q, const float* __restrict__ K)
{
    const int g   = blockIdx.x * 256 + threadIdx.x;   // one (row, 16-col blk)
    const size_t off = (size_t)(g >> 2) * DHEAD + ((g & 3) << 4);

    float4 f0 = *(const float4*)(Q + off);
    float4 f1 = *(const float4*)(Q + off + 4);
    float4 f2 = *(const float4*)(Q + off + 8);
    float4 f3 = *(const float4*)(Q + off + 12);
    uint4 a, b;
    a.x = packh2(f0.x * 0.125f, f0.y * 0.125f);
    a.y = packh2(f2.x * 0.125f, f2.y * 0.125f);
    a.z = packh2(f0.z * 0.125f, f0.w * 0.125f);
    a.w = packh2(f2.z * 0.125f, f2.w * 0.125f);
    b.x = packh2(f1.x * 0.125f, f1.y * 0.125f);
    b.y = packh2(f3.x * 0.125f, f3.y * 0.125f);
    b.z = packh2(f1.z * 0.125f, f1.w * 0.125f);
    b.w = packh2(f3.z * 0.125f, f3.w * 0.125f);
    *(uint4*)(g_Qh + off)     = a;
    *(uint4*)(g_Qh + off + 8) = b;

    f0 = *(const float4*)(K + off);
    f1 = *(const float4*)(K + off + 4);
    f2 = *(const float4*)(K + off + 8);
    f3 = *(const float4*)(K + off + 12);
    a.x = packh2(f0.x, f0.y);  a.y = packh2(f2.x, f2.y);
    a.z = packh2(f0.z, f0.w);  a.w = packh2(f2.z, f2.w);
    b.x = packh2(f1.x, f1.y);  b.y = packh2(f3.x, f3.y);
    b.z = packh2(f1.z, f1.w);  b.w = packh2(f3.z, f3.w);
    *(uint4*)(g_Kh + off)     = a;
    *(uint4*)(g_Kh + off + 8) = b;
}

// ---- prep 2: V -> fp16, transposed [d][k] per head, k-interleaved ----
__global__ void __launch_bounds__(256)
prep_vt(const float* __restrict__ V)
{
    __shared__ float ts[64][68];   // 272B row stride: float4-aligned every row
    const int tid = threadIdx.x;
    const int kt0 = blockIdx.x * 64;
    const int bh  = blockIdx.y;
    const float* vsrc = V + (size_t)bh * L_SEQ * DHEAD;
    __half* vdst = g_Vth + (size_t)bh * DHEAD * L_SEQ;

    #pragma unroll
    for (int i = 0; i < 4; ++i) {
        const int idx = tid + 256 * i;
        const int row = idx >> 4, c4 = (idx & 15) << 2;
        *(float4*)&ts[row][c4] =
            *(const float4*)(vsrc + (size_t)(kt0 + row) * DHEAD + c4);
    }
    __syncthreads();

    const int d  = tid >> 2;
    const int kb = (tid & 3) << 4;   // local k-block of 16
    uint4 a, b;
    a.x = packh2(ts[kb + 0][d],  ts[kb + 1][d]);
    a.y = packh2(ts[kb + 8][d],  ts[kb + 9][d]);
    a.z = packh2(ts[kb + 2][d],  ts[kb + 3][d]);
    a.w = packh2(ts[kb + 10][d], ts[kb + 11][d]);
    b.x = packh2(ts[kb + 4][d],  ts[kb + 5][d]);
    b.y = packh2(ts[kb + 12][d], ts[kb + 13][d]);
    b.z = packh2(ts[kb + 6][d],  ts[kb + 7][d]);
    b.w = packh2(ts[kb + 14][d], ts[kb + 15][d]);
    __half* dst = vdst + (size_t)d * L_SEQ + kt0 + kb;
    *(uint4*)dst       = a;
    *(uint4*)(dst + 8) = b;
}

// ---- main kernel ----
__global__ void __launch_bounds__(256, 2)
taylor_attn_h(float* __restrict__ O)
{
    extern __shared__ __half smh[];
    __half* Qs = smh;                      // [128][72]
    __half* Kb = Qs + BM * QS;             // [2][128][72]
    __half* Vb = Kb + 2 * BN * QS;         // [2][64][136]
    const uint32_t sQs = smem_u32(Qs);
    const uint32_t sKb = smem_u32(Kb);
    const uint32_t sVb = smem_u32(Vb);

    const int tid  = threadIdx.x;
    const int wid  = tid >> 5;
    const int lane = tid & 31;
    const int grp  = lane >> 2;
    const int c    = lane & 3;
    const int qt   = (int)gridDim.x - 1 - (int)blockIdx.x;   // big tiles first
    const int bh   = blockIdx.y;
    const int qbase = qt * BM;

    const int rloc = 16 * wid + grp;
    const int rg   = qbase + rloc;
    const int rmax = 16 * wid + 15;        // warp's max local row

    const __half* Qg = g_Qh + (size_t)bh * L_SEQ * DHEAD;
    const __half* Kg = g_Kh + (size_t)bh * L_SEQ * DHEAD;
    const __half* Vg = g_Vth + (size_t)bh * DHEAD * L_SEQ;

    // ---- prologue: Q tile + K/V tile 0 ----
    #pragma unroll
    for (int i = 0; i < 4; ++i) {
        const int idx = tid + 256 * i;
        const int row = idx >> 3, ch = idx & 7;
        cp16(sQs + (uint32_t)(row * QS + ch * 8) * 2,
             Qg + (size_t)(qbase + row) * DHEAD + ch * 8);
        cp16(sKb + (uint32_t)(row * QS + ch * 8) * 2,
             Kg + (size_t)row * DHEAD + ch * 8);
    }
    #pragma unroll
    for (int i = 0; i < 4; ++i) {
        const int idx = tid + 256 * i;
        const int row = idx >> 4, ch = idx & 15;
        cp16(sVb + (uint32_t)(row * VTS + ch * 8) * 2,
             Vg + (size_t)row * L_SEQ + ch * 8);
    }
    cp_commit();

    float oacc[8][4];
    #pragma unroll
    for (int t = 0; t < 8; ++t)
        #pragma unroll
        for (int j = 0; j < 4; ++j) oacc[t][j] = 0.0f;
    float zr0 = 0.0f, zr1 = 0.0f;

    for (int j = 0; j <= qt; ++j) {
        const int buf = j & 1;

        if (j < qt) {   // prefetch tile j+1
            const int nb = buf ^ 1;
            const int kb1 = (j + 1) * BN;
            const uint32_t dK = sKb + (uint32_t)(nb * BN * QS) * 2;
            const uint32_t dV = sVb + (uint32_t)(nb * 64 * VTS) * 2;
            #pragma unroll
            for (int i = 0; i < 4; ++i) {
                const int idx = tid + 256 * i;
                const int rowk = idx >> 3, chk = idx & 7;
                cp16(dK + (uint32_t)(rowk * QS + chk * 8) * 2,
                     Kg + (size_t)(kb1 + rowk) * DHEAD + chk * 8);
                const int rowv = idx >> 4, chv = idx & 15;
                cp16(dV + (uint32_t)(rowv * VTS + chv * 8) * 2,
                     Vg + (size_t)rowv * L_SEQ + kb1 + chv * 8);
            }
            cp_commit();
            cp_wait1();
        } else {
            cp_wait0();
        }
        __syncthreads();

        const __half* Kt  = Kb + buf * BN * QS;
        const __half* Vtb = Vb + buf * 64 * VTS;
        const int kbase = j * BN;
        const bool diag = (j == qt);

        #pragma unroll
        for (int h = 0; h < 2; ++h) {
            if (diag && 64 * h > rmax) continue;   // fully-masked half

            // ---- MMA1: S (16 x 64 per warp-half) = Q @ K^T ----
            float sacc[8][4];
            #pragma unroll
            for (int t = 0; t < 8; ++t)
                #pragma unroll
                for (int jj = 0; jj < 4; ++jj) sacc[t][jj] = 0.0f;

            #pragma unroll
            for (int d = 0; d < 4; ++d) {
                const uint2 qa = *(const uint2*)(Qs + rloc * QS + 16 * d + 4 * c);
                const uint2 qb = *(const uint2*)(Qs + (rloc + 8) * QS + 16 * d + 4 * c);
                #pragma unroll
                for (int t = 0; t < 8; ++t) {
                    const uint2 kf = *(const uint2*)
                        (Kt + (64 * h + 8 * t + grp) * QS + 16 * d + 4 * c);
                    mma16(sacc[t], qa.x, qb.x, qa.y, qb.y, kf.x, kf.y);
                }
            }

            // ---- epilogue: f(s), mask, z, pack to half2 ----
            uint32_t pr[8][2];
            #pragma unroll
            for (int t = 0; t < 8; ++t) {
                const int cb = kbase + 64 * h + 8 * t + 2 * c;
                float s0 = sacc[t][0], s1 = sacc[t][1];
                float s2 = sacc[t][2], s3 = sacc[t][3];
                float p0 = fmaf(fmaf(0.5f, s0, 1.0f), s0, 1.0f);
                float p1 = fmaf(fmaf(0.5f, s1, 1.0f), s1, 1.0f);
                float p2 = fmaf(fmaf(0.5f, s2, 1.0f), s2, 1.0f);
                float p3 = fmaf(fmaf(0.5f, s3, 1.0f), s3, 1.0f);
                if (diag) {
                    if (cb     > rg)     p0 = 0.0f;
                    if (cb + 1 > rg)     p1 = 0.0f;
                    if (cb     > rg + 8) p2 = 0.0f;
                    if (cb + 1 > rg + 8) p3 = 0.0f;
                }
                zr0 += p0 + p1;
                zr1 += p2 + p3;
                pr[t][0] = packh2(p0, p1);
                pr[t][1] = packh2(p2, p3);
            }

            // ---- MMA2: O += P @ V ; A-frag = C-frags of tiles 2u,2u+1 ----
            #pragma unroll
            for (int u = 0; u < 4; ++u) {
                if (diag && 64 * h + 16 * u > rmax) continue;
                const uint32_t a0 = pr[2 * u][0];
                const uint32_t a1 = pr[2 * u][1];
                const uint32_t a2 = pr[2 * u + 1][0];
                const uint32_t a3 = pr[2 * u + 1][1];
                const int vcol = 16 * (4 * h + u) + 4 * c;
                #pragma unroll
                for (int tn = 0; tn < 8; ++tn) {
                    const uint2 vf = *(const uint2*)
                        (Vtb + (8 * tn + grp) * VTS + vcol);
                    mma16(oacc[tn], a0, a1, a2, a3, vf.x, vf.y);
                }
            }
        }
        __syncthreads();
    }

    // ---- z reduce across the 4 lanes of each row-group ----
    zr0 += __shfl_xor_sync(0xffffffffu, zr0, 1);
    zr0 += __shfl_xor_sync(0xffffffffu, zr0, 2);
    zr1 += __shfl_xor_sync(0xffffffffu, zr1, 1);
    zr1 += __shfl_xor_sync(0xffffffffu, zr1, 2);
    const float inv0 = 1.0f / (zr0 + 1e-6f);
    const float inv1 = 1.0f / (zr1 + 1e-6f);

    float* ob0 = O + (size_t)bh * L_SEQ * DHEAD + (size_t)rg * DHEAD + 2 * c;
    float* ob1 = ob0 + 8 * DHEAD;
    #pragma unroll
    for (int tn = 0; tn < 8; ++tn) {
        float2 w0; w0.x = oacc[tn][0] * inv0; w0.y = oacc[tn][1] * inv0;
        float2 w1; w1.x = oacc[tn][2] * inv1; w1.y = oacc[tn][3] * inv1;
        *(float2*)(ob0 + 8 * tn) = w0;
        *(float2*)(ob1 + 8 * tn) = w1;
    }
}

extern "C" void kernel_launch(void* const* d_in, const int* in_sizes, int n_in,
                              void* d_out, int out_size) {
    (void)in_sizes; (void)n_in; (void)out_size;
    const float* q = (const float*)d_in[0];
    const float* k = (const float*)d_in[1];
    const float* v = (const float*)d_in[2];
    float* o = (float*)d_out;

    const int smem_bytes = (BM * QS + 2 * BN * QS + 2 * 64 * VTS) * 2;  // 90112 B
    static bool configured = false;
    if (!configured) {
        cudaFuncSetAttribute(taylor_attn_h,
                             cudaFuncAttributeMaxDynamicSharedMemorySize, smem_bytes);
        configured = true;
    }

    prep_qk<<<(NBH * L_SEQ * (DHEAD / 16)) / 256, 256>>>(q, k);
    prep_vt<<<dim3(L_SEQ / 64, NBH), 256>>>(v);

    dim3 grid(L_SEQ / BM, NBH);
    taylor_attn_h<<<grid, 256, smem_bytes>>>(o);
}

// round 8
// speedup vs baseline: 6.9422x; 1.3993x over previous
#include <cuda_runtime.h>
#include <cuda_fp16.h>
#include <cstdint>

// Taylor causal attention, fp16 mma.sync m16n8k16 (fp32 accum), cp.async
// double-buffered, global-LPT CTA ordering, diag-tile MMA skipping.
// B=2,H=16,L=2048,D=64. CTA: 128 q-rows, 8 warps, k-tiles of 128.

#define L_SEQ 2048
#define DHEAD 64
#define NBH   32
#define BM    128
#define BN    128
#define QS    72     // Q/K smem row stride in halves (144B; deg-2 banks)
#define VTS   136    // Vt smem row stride in halves (272B; deg-2 banks)

__device__ __align__(16) __half g_Qh[NBH * L_SEQ * DHEAD];  // scaled, interleaved
__device__ __align__(16) __half g_Kh[NBH * L_SEQ * DHEAD];  // interleaved
__device__ __align__(16) __half g_Vth[NBH * DHEAD * L_SEQ]; // [d][k], k-interleaved

static __device__ __forceinline__ uint32_t packh2(float lo, float hi) {
    __half2 h = __floats2half2_rn(lo, hi);
    return *(uint32_t*)&h;
}
static __device__ __forceinline__ uint32_t smem_u32(const void* p) {
    uint32_t a;
    asm("{ .reg .u64 t; cvta.to.shared.u64 t, %1; cvt.u32.u64 %0, t; }" : "=r"(a) : "l"(p));
    return a;
}
static __device__ __forceinline__ void cp16(uint32_t s, const void* g) {
    asm volatile("cp.async.cg.shared.global [%0], [%1], 16;"
                 :: "r"(s), "l"(__cvta_generic_to_global(g)));
}
static __device__ __forceinline__ void cp_commit() {
    asm volatile("cp.async.commit_group;" ::: "memory");
}
static __device__ __forceinline__ void cp_wait1() {
    asm volatile("cp.async.wait_group 1;" ::: "memory");
}
static __device__ __forceinline__ void cp_wait0() {
    asm volatile("cp.async.wait_group 0;" ::: "memory");
}
static __device__ __forceinline__ void mma16(float* d,
        uint32_t a0, uint32_t a1, uint32_t a2, uint32_t a3,
        uint32_t b0, uint32_t b1) {
    asm volatile(
        "mma.sync.aligned.m16n8k16.row.col.f32.f16.f16.f32 "
        "{%0,%1,%2,%3}, {%4,%5,%6,%7}, {%8,%9}, {%0,%1,%2,%3};"
        : "+f"(d[0]), "+f"(d[1]), "+f"(d[2]), "+f"(d[3])
        : "r"(a0), "r"(a1), "r"(a2), "r"(a3), "r"(b0), "r"(b1));
}

// ---- merged prep: y=0 -> Q,K convert+interleave; y=1 -> V transpose ----
__global__ void __launch_bounds__(256)
prep_all(const float* __restrict__ Q, const float* __restrict__ K,
         const float* __restrict__ V)
{
    if (blockIdx.y == 0) {
        // Q,K -> fp16, interleaved per 16-col block (Q pre-scaled)
        const int g   = blockIdx.x * 256 + threadIdx.x;
        const size_t off = (size_t)(g >> 2) * DHEAD + ((g & 3) << 4);

        float4 f0 = *(const float4*)(Q + off);
        float4 f1 = *(const float4*)(Q + off + 4);
        float4 f2 = *(const float4*)(Q + off + 8);
        float4 f3 = *(const float4*)(Q + off + 12);
        uint4 a, b;
        a.x = packh2(f0.x * 0.125f, f0.y * 0.125f);
        a.y = packh2(f2.x * 0.125f, f2.y * 0.125f);
        a.z = packh2(f0.z * 0.125f, f0.w * 0.125f);
        a.w = packh2(f2.z * 0.125f, f2.w * 0.125f);
        b.x = packh2(f1.x * 0.125f, f1.y * 0.125f);
        b.y = packh2(f3.x * 0.125f, f3.y * 0.125f);
        b.z = packh2(f1.z * 0.125f, f1.w * 0.125f);
        b.w = packh2(f3.z * 0.125f, f3.w * 0.125f);
        *(uint4*)(g_Qh + off)     = a;
        *(uint4*)(g_Qh + off + 8) = b;

        f0 = *(const float4*)(K + off);
        f1 = *(const float4*)(K + off + 4);
        f2 = *(const float4*)(K + off + 8);
        f3 = *(const float4*)(K + off + 12);
        a.x = packh2(f0.x, f0.y);  a.y = packh2(f2.x, f2.y);
        a.z = packh2(f0.z, f0.w);  a.w = packh2(f2.z, f2.w);
        b.x = packh2(f1.x, f1.y);  b.y = packh2(f3.x, f3.y);
        b.z = packh2(f1.z, f1.w);  b.w = packh2(f3.z, f3.w);
        *(uint4*)(g_Kh + off)     = a;
        *(uint4*)(g_Kh + off + 8) = b;
    } else {
        // V -> fp16, transposed [d][k] per head, k-interleaved
        __shared__ float ts[64][68];   // 272B rows: float4-aligned every row
        const int tid = threadIdx.x;
        const int kt0 = (blockIdx.x & 31) * 64;
        const int bh  = blockIdx.x >> 5;
        const float* vsrc = V + (size_t)bh * L_SEQ * DHEAD;
        __half* vdst = g_Vth + (size_t)bh * DHEAD * L_SEQ;

        #pragma unroll
        for (int i = 0; i < 4; ++i) {
            const int idx = tid + 256 * i;
            const int row = idx >> 4, c4 = (idx & 15) << 2;
            *(float4*)&ts[row][c4] =
                *(const float4*)(vsrc + (size_t)(kt0 + row) * DHEAD + c4);
        }
        __syncthreads();

        const int d  = tid >> 2;
        const int kb = (tid & 3) << 4;
        uint4 a, b;
        a.x = packh2(ts[kb + 0][d],  ts[kb + 1][d]);
        a.y = packh2(ts[kb + 8][d],  ts[kb + 9][d]);
        a.z = packh2(ts[kb + 2][d],  ts[kb + 3][d]);
        a.w = packh2(ts[kb + 10][d], ts[kb + 11][d]);
        b.x = packh2(ts[kb + 4][d],  ts[kb + 5][d]);
        b.y = packh2(ts[kb + 12][d], ts[kb + 13][d]);
        b.z = packh2(ts[kb + 6][d],  ts[kb + 7][d]);
        b.w = packh2(ts[kb + 14][d], ts[kb + 15][d]);
        __half* dst = vdst + (size_t)d * L_SEQ + kt0 + kb;
        *(uint4*)dst       = a;
        *(uint4*)(dst + 8) = b;
    }
}

// ---- main kernel ----
__global__ void __launch_bounds__(256, 2)
taylor_attn_h(float* __restrict__ O)
{
    extern __shared__ __half smh[];
    __half* Qs = smh;                      // [128][72]
    __half* Kb = Qs + BM * QS;             // [2][128][72]
    __half* Vb = Kb + 2 * BN * QS;         // [2][64][136]
    const uint32_t sQs = smem_u32(Qs);
    const uint32_t sKb = smem_u32(Kb);
    const uint32_t sVb = smem_u32(Vb);

    const int tid  = threadIdx.x;
    const int wid  = tid >> 5;
    const int lane = tid & 31;
    const int grp  = lane >> 2;
    const int c    = lane & 3;
    // global LPT: biggest q-tiles first across all heads
    const int qt   = (L_SEQ / BM) - 1 - ((int)blockIdx.x >> 5);
    const int bh   = (int)blockIdx.x & 31;
    const int qbase = qt * BM;

    const int rloc = 16 * wid + grp;
    const int rg   = qbase + rloc;
    const int rmax = 16 * wid + 15;        // warp's max local row

    const __half* Qg = g_Qh + (size_t)bh * L_SEQ * DHEAD;
    const __half* Kg = g_Kh + (size_t)bh * L_SEQ * DHEAD;
    const __half* Vg = g_Vth + (size_t)bh * DHEAD * L_SEQ;

    // ---- prologue: Q tile + K/V tile 0 ----
    #pragma unroll
    for (int i = 0; i < 4; ++i) {
        const int idx = tid + 256 * i;
        const int row = idx >> 3, ch = idx & 7;
        cp16(sQs + (uint32_t)(row * QS + ch * 8) * 2,
             Qg + (size_t)(qbase + row) * DHEAD + ch * 8);
        cp16(sKb + (uint32_t)(row * QS + ch * 8) * 2,
             Kg + (size_t)row * DHEAD + ch * 8);
    }
    #pragma unroll
    for (int i = 0; i < 4; ++i) {
        const int idx = tid + 256 * i;
        const int row = idx >> 4, ch = idx & 15;
        cp16(sVb + (uint32_t)(row * VTS + ch * 8) * 2,
             Vg + (size_t)row * L_SEQ + ch * 8);
    }
    cp_commit();

    float oacc[8][4];
    #pragma unroll
    for (int t = 0; t < 8; ++t)
        #pragma unroll
        for (int j = 0; j < 4; ++j) oacc[t][j] = 0.0f;
    float zr0 = 0.0f, zr1 = 0.0f;

    for (int j = 0; j <= qt; ++j) {
        const int buf = j & 1;

        if (j < qt) {   // prefetch tile j+1
            const int nb = buf ^ 1;
            const int kb1 = (j + 1) * BN;
            const uint32_t dK = sKb + (uint32_t)(nb * BN * QS) * 2;
            const uint32_t dV = sVb + (uint32_t)(nb * 64 * VTS) * 2;
            #pragma unroll
            for (int i = 0; i < 4; ++i) {
                const int idx = tid + 256 * i;
                const int rowk = idx >> 3, chk = idx & 7;
                cp16(dK + (uint32_t)(rowk * QS + chk * 8) * 2,
                     Kg + (size_t)(kb1 + rowk) * DHEAD + chk * 8);
                const int rowv = idx >> 4, chv = idx & 15;
                cp16(dV + (uint32_t)(rowv * VTS + chv * 8) * 2,
                     Vg + (size_t)rowv * L_SEQ + kb1 + chv * 8);
            }
            cp_commit();
            cp_wait1();
        } else {
            cp_wait0();
        }
        __syncthreads();

        const __half* Kt  = Kb + buf * BN * QS;
        const __half* Vtb = Vb + buf * 64 * VTS;
        const int kbase = j * BN;
        const bool diag = (j == qt);

        #pragma unroll
        for (int h = 0; h < 2; ++h) {
            if (diag && 64 * h > rmax) continue;   // fully-masked half
            const int tcap = diag ? ((rmax - 64 * h) >> 3) : 7;  // last live t

            // ---- MMA1: S (16 x 64 per warp-half) = Q @ K^T ----
            float sacc[8][4];
            #pragma unroll
            for (int t = 0; t < 8; ++t)
                #pragma unroll
                for (int jj = 0; jj < 4; ++jj) sacc[t][jj] = 0.0f;

            #pragma unroll
            for (int d = 0; d < 4; ++d) {
                const uint2 qa = *(const uint2*)(Qs + rloc * QS + 16 * d + 4 * c);
                const uint2 qb = *(const uint2*)(Qs + (rloc + 8) * QS + 16 * d + 4 * c);
                #pragma unroll
                for (int t = 0; t < 8; ++t) {
                    if (t > tcap) break;   // diag: cols fully above all rows
                    const uint2 kf = *(const uint2*)
                        (Kt + (64 * h + 8 * t + grp) * QS + 16 * d + 4 * c);
                    mma16(sacc[t], qa.x, qb.x, qa.y, qb.y, kf.x, kf.y);
                }
            }

            // ---- epilogue: f(s), mask, z, pack to half2 ----
            uint32_t pr[8][2];
            #pragma unroll
            for (int t = 0; t < 8; ++t) { pr[t][0] = 0u; pr[t][1] = 0u; }
            #pragma unroll
            for (int t = 0; t < 8; ++t) {
                if (t > tcap) break;
                const int cb = kbase + 64 * h + 8 * t + 2 * c;
                float s0 = sacc[t][0], s1 = sacc[t][1];
                float s2 = sacc[t][2], s3 = sacc[t][3];
                float p0 = fmaf(fmaf(0.5f, s0, 1.0f), s0, 1.0f);
                float p1 = fmaf(fmaf(0.5f, s1, 1.0f), s1, 1.0f);
                float p2 = fmaf(fmaf(0.5f, s2, 1.0f), s2, 1.0f);
                float p3 = fmaf(fmaf(0.5f, s3, 1.0f), s3, 1.0f);
                if (diag) {
                    if (cb     > rg)     p0 = 0.0f;
                    if (cb + 1 > rg)     p1 = 0.0f;
                    if (cb     > rg + 8) p2 = 0.0f;
                    if (cb + 1 > rg + 8) p3 = 0.0f;
                }
                zr0 += p0 + p1;
                zr1 += p2 + p3;
                pr[t][0] = packh2(p0, p1);
                pr[t][1] = packh2(p2, p3);
            }

            // ---- MMA2: O += P @ V ; A-frag = C-frags of tiles 2u,2u+1 ----
            #pragma unroll
            for (int u = 0; u < 4; ++u) {
                if (diag && 64 * h + 16 * u > rmax) break;
                const uint32_t a0 = pr[2 * u][0];
                const uint32_t a1 = pr[2 * u][1];
                const uint32_t a2 = pr[2 * u + 1][0];
                const uint32_t a3 = pr[2 * u + 1][1];
                const int vcol = 16 * (4 * h + u) + 4 * c;
                #pragma unroll
                for (int tn = 0; tn < 8; ++tn) {
                    const uint2 vf = *(const uint2*)
                        (Vtb + (8 * tn + grp) * VTS + vcol);
                    mma16(oacc[tn], a0, a1, a2, a3, vf.x, vf.y);
                }
            }
        }
        __syncthreads();
    }

    // ---- z reduce across the 4 lanes of each row-group ----
    zr0 += __shfl_xor_sync(0xffffffffu, zr0, 1);
    zr0 += __shfl_xor_sync(0xffffffffu, zr0, 2);
    zr1 += __shfl_xor_sync(0xffffffffu, zr1, 1);
    zr1 += __shfl_xor_sync(0xffffffffu, zr1, 2);
    const float inv0 = 1.0f / (zr0 + 1e-6f);
    const float inv1 = 1.0f / (zr1 + 1e-6f);

    float* ob0 = O + (size_t)bh * L_SEQ * DHEAD + (size_t)rg * DHEAD + 2 * c;
    float* ob1 = ob0 + 8 * DHEAD;
    #pragma unroll
    for (int tn = 0; tn < 8; ++tn) {
        float2 w0; w0.x = oacc[tn][0] * inv0; w0.y = oacc[tn][1] * inv0;
        float2 w1; w1.x = oacc[tn][2] * inv1; w1.y = oacc[tn][3] * inv1;
        *(float2*)(ob0 + 8 * tn) = w0;
        *(float2*)(ob1 + 8 * tn) = w1;
    }
}

extern "C" void kernel_launch(void* const* d_in, const int* in_sizes, int n_in,
                              void* d_out, int out_size) {
    (void)in_sizes; (void)n_in; (void)out_size;
    const float* q = (const float*)d_in[0];
    const float* k = (const float*)d_in[1];
    const float* v = (const float*)d_in[2];
    float* o = (float*)d_out;

    const int smem_bytes = (BM * QS + 2 * BN * QS + 2 * 64 * VTS) * 2;  // 90112 B
    static bool configured = false;
    if (!configured) {
        cudaFuncSetAttribute(taylor_attn_h,
                             cudaFuncAttributeMaxDynamicSharedMemorySize, smem_bytes);
        configured = true;
    }

    prep_all<<<dim3(1024, 2), 256>>>(q, k, v);

    dim3 grid((L_SEQ / BM) * NBH);   // 512, global LPT order
    taylor_attn_h<<<grid, 256, smem_bytes>>>(o);
}

// round 9
// speedup vs baseline: 7.1351x; 1.0278x over previous
#include <cuda_runtime.h>
#include <cuda_fp16.h>
#include <cstdint>

// Taylor causal attention, fp16 mma.sync m16n8k16 (fp32 accum).
// 2-D warp tiling (4 row-groups x 2 col-groups) to cut redundant K/V
// fragment LDS traffic; O partials reduced across col-groups once at the end.
// cp.async double-buffered, global-LPT CTA ordering, diag skipping.
// B=2,H=16,L=2048,D=64. CTA: 128 q-rows, 8 warps, k-tiles of 128.

#define L_SEQ 2048
#define DHEAD 64
#define NBH   32
#define BM    128
#define BN    128
#define QS    72     // Q/K smem row stride in halves (144B; deg-2 banks)
#define VTS   136    // Vt smem row stride in halves (272B; deg-2 banks)
#define OS    66     // O-partial reduction row stride (floats)

__device__ __align__(16) __half g_Qh[NBH * L_SEQ * DHEAD];  // scaled, interleaved
__device__ __align__(16) __half g_Kh[NBH * L_SEQ * DHEAD];  // interleaved
__device__ __align__(16) __half g_Vth[NBH * DHEAD * L_SEQ]; // [d][k], k-interleaved

static __device__ __forceinline__ uint32_t packh2(float lo, float hi) {
    __half2 h = __floats2half2_rn(lo, hi);
    return *(uint32_t*)&h;
}
static __device__ __forceinline__ uint32_t smem_u32(const void* p) {
    uint32_t a;
    asm("{ .reg .u64 t; cvta.to.shared.u64 t, %1; cvt.u32.u64 %0, t; }" : "=r"(a) : "l"(p));
    return a;
}
static __device__ __forceinline__ void cp16(uint32_t s, const void* g) {
    asm volatile("cp.async.cg.shared.global [%0], [%1], 16;"
                 :: "r"(s), "l"(__cvta_generic_to_global(g)));
}
static __device__ __forceinline__ void cp_commit() {
    asm volatile("cp.async.commit_group;" ::: "memory");
}
static __device__ __forceinline__ void cp_wait1() {
    asm volatile("cp.async.wait_group 1;" ::: "memory");
}
static __device__ __forceinline__ void cp_wait0() {
    asm volatile("cp.async.wait_group 0;" ::: "memory");
}
static __device__ __forceinline__ void mma16(float* d,
        uint32_t a0, uint32_t a1, uint32_t a2, uint32_t a3,
        uint32_t b0, uint32_t b1) {
    asm volatile(
        "mma.sync.aligned.m16n8k16.row.col.f32.f16.f16.f32 "
        "{%0,%1,%2,%3}, {%4,%5,%6,%7}, {%8,%9}, {%0,%1,%2,%3};"
        : "+f"(d[0]), "+f"(d[1]), "+f"(d[2]), "+f"(d[3])
        : "r"(a0), "r"(a1), "r"(a2), "r"(a3), "r"(b0), "r"(b1));
}

// ---- merged prep: y=0 -> Q,K convert+interleave; y=1 -> V transpose ----
__global__ void __launch_bounds__(256)
prep_all(const float* __restrict__ Q, const float* __restrict__ K,
         const float* __restrict__ V)
{
    if (blockIdx.y == 0) {
        const int g   = blockIdx.x * 256 + threadIdx.x;
        const size_t off = (size_t)(g >> 2) * DHEAD + ((g & 3) << 4);

        float4 f0 = *(const float4*)(Q + off);
        float4 f1 = *(const float4*)(Q + off + 4);
        float4 f2 = *(const float4*)(Q + off + 8);
        float4 f3 = *(const float4*)(Q + off + 12);
        uint4 a, b;
        a.x = packh2(f0.x * 0.125f, f0.y * 0.125f);
        a.y = packh2(f2.x * 0.125f, f2.y * 0.125f);
        a.z = packh2(f0.z * 0.125f, f0.w * 0.125f);
        a.w = packh2(f2.z * 0.125f, f2.w * 0.125f);
        b.x = packh2(f1.x * 0.125f, f1.y * 0.125f);
        b.y = packh2(f3.x * 0.125f, f3.y * 0.125f);
        b.z = packh2(f1.z * 0.125f, f1.w * 0.125f);
        b.w = packh2(f3.z * 0.125f, f3.w * 0.125f);
        *(uint4*)(g_Qh + off)     = a;
        *(uint4*)(g_Qh + off + 8) = b;

        f0 = *(const float4*)(K + off);
        f1 = *(const float4*)(K + off + 4);
        f2 = *(const float4*)(K + off + 8);
        f3 = *(const float4*)(K + off + 12);
        a.x = packh2(f0.x, f0.y);  a.y = packh2(f2.x, f2.y);
        a.z = packh2(f0.z, f0.w);  a.w = packh2(f2.z, f2.w);
        b.x = packh2(f1.x, f1.y);  b.y = packh2(f3.x, f3.y);
        b.z = packh2(f1.z, f1.w);  b.w = packh2(f3.z, f3.w);
        *(uint4*)(g_Kh + off)     = a;
        *(uint4*)(g_Kh + off + 8) = b;
    } else {
        __shared__ float ts[64][68];
        const int tid = threadIdx.x;
        const int kt0 = (blockIdx.x & 31) * 64;
        const int bh  = blockIdx.x >> 5;
        const float* vsrc = V + (size_t)bh * L_SEQ * DHEAD;
        __half* vdst = g_Vth + (size_t)bh * DHEAD * L_SEQ;

        #pragma unroll
        for (int i = 0; i < 4; ++i) {
            const int idx = tid + 256 * i;
            const int row = idx >> 4, c4 = (idx & 15) << 2;
            *(float4*)&ts[row][c4] =
                *(const float4*)(vsrc + (size_t)(kt0 + row) * DHEAD + c4);
        }
        __syncthreads();

        const int d  = tid >> 2;
        const int kb = (tid & 3) << 4;
        uint4 a, b;
        a.x = packh2(ts[kb + 0][d],  ts[kb + 1][d]);
        a.y = packh2(ts[kb + 8][d],  ts[kb + 9][d]);
        a.z = packh2(ts[kb + 2][d],  ts[kb + 3][d]);
        a.w = packh2(ts[kb + 10][d], ts[kb + 11][d]);
        b.x = packh2(ts[kb + 4][d],  ts[kb + 5][d]);
        b.y = packh2(ts[kb + 12][d], ts[kb + 13][d]);
        b.z = packh2(ts[kb + 6][d],  ts[kb + 7][d]);
        b.w = packh2(ts[kb + 14][d], ts[kb + 15][d]);
        __half* dst = vdst + (size_t)d * L_SEQ + kt0 + kb;
        *(uint4*)dst       = a;
        *(uint4*)(dst + 8) = b;
    }
}

// ---- main kernel ----
__global__ void __launch_bounds__(256, 2)
taylor_attn_h(float* __restrict__ O)
{
    extern __shared__ __half smh[];
    __half* Qs = smh;                      // [128][72]
    __half* Kb = Qs + BM * QS;             // [2][128][72]
    __half* Vb = Kb + 2 * BN * QS;         // [2][64][136]
    const uint32_t sQs = smem_u32(Qs);
    const uint32_t sKb = smem_u32(Kb);
    const uint32_t sVb = smem_u32(Vb);

    const int tid  = threadIdx.x;
    const int wid  = tid >> 5;
    const int lane = tid & 31;
    const int grp  = lane >> 2;
    const int c    = lane & 3;
    const int mw   = wid & 3;              // row group (32 rows)
    const int nw   = wid >> 2;             // col group (64 cols)
    const int rbase = 32 * mw;
    const int colw  = 64 * nw;
    // global LPT: biggest q-tiles first across all heads
    const int qt   = (L_SEQ / BM) - 1 - ((int)blockIdx.x >> 5);
    const int bh   = (int)blockIdx.x & 31;
    const int qbase = qt * BM;

    const __half* Qg = g_Qh + (size_t)bh * L_SEQ * DHEAD;
    const __half* Kg = g_Kh + (size_t)bh * L_SEQ * DHEAD;
    const __half* Vg = g_Vth + (size_t)bh * DHEAD * L_SEQ;

    // ---- prologue: Q tile + K/V tile 0 ----
    #pragma unroll
    for (int i = 0; i < 4; ++i) {
        const int idx = tid + 256 * i;
        const int row = idx >> 3, ch = idx & 7;
        cp16(sQs + (uint32_t)(row * QS + ch * 8) * 2,
             Qg + (size_t)(qbase + row) * DHEAD + ch * 8);
        cp16(sKb + (uint32_t)(row * QS + ch * 8) * 2,
             Kg + (size_t)row * DHEAD + ch * 8);
    }
    #pragma unroll
    for (int i = 0; i < 4; ++i) {
        const int idx = tid + 256 * i;
        const int row = idx >> 4, ch = idx & 15;
        cp16(sVb + (uint32_t)(row * VTS + ch * 8) * 2,
             Vg + (size_t)row * L_SEQ + ch * 8);
    }
    cp_commit();

    float oacc[2][8][4];          // [m-tile][d-tile][frag]
    #pragma unroll
    for (int mi = 0; mi < 2; ++mi)
        #pragma unroll
        for (int t = 0; t < 8; ++t)
            #pragma unroll
            for (int j = 0; j < 4; ++j) oacc[mi][t][j] = 0.0f;
    float zr[2][2] = {};

    for (int j = 0; j <= qt; ++j) {
        const int buf = j & 1;

        if (j < qt) {   // prefetch tile j+1
            const int nb = buf ^ 1;
            const int kb1 = (j + 1) * BN;
            const uint32_t dK = sKb + (uint32_t)(nb * BN * QS) * 2;
            const uint32_t dV = sVb + (uint32_t)(nb * 64 * VTS) * 2;
            #pragma unroll
            for (int i = 0; i < 4; ++i) {
                const int idx = tid + 256 * i;
                const int rowk = idx >> 3, chk = idx & 7;
                cp16(dK + (uint32_t)(rowk * QS + chk * 8) * 2,
                     Kg + (size_t)(kb1 + rowk) * DHEAD + chk * 8);
                const int rowv = idx >> 4, chv = idx & 15;
                cp16(dV + (uint32_t)(rowv * VTS + chv * 8) * 2,
                     Vg + (size_t)rowv * L_SEQ + kb1 + chv * 8);
            }
            cp_commit();
            cp_wait1();
        } else {
            cp_wait0();
        }
        __syncthreads();

        const __half* Kt  = Kb + buf * BN * QS;
        const __half* Vtb = Vb + buf * 64 * VTS;
        const int kbase = j * BN;
        const bool diag = (j == qt);

        #pragma unroll
        for (int ch = 0; ch < 2; ++ch) {     // warp's two 32-col chunks
            const int cb0 = colw + 32 * ch;  // chunk column base in tile
            if (diag && cb0 > rbase + 31) continue;
            const int tcap = diag ? ((rbase + 31 - cb0) >> 3) : 3;

            // ---- MMA1: S chunk (32 rows x 32 cols) = Q @ K^T ----
            float sacc[2][4][4];
            #pragma unroll
            for (int mi = 0; mi < 2; ++mi)
                #pragma unroll
                for (int t = 0; t < 4; ++t)
                    #pragma unroll
                    for (int jj = 0; jj < 4; ++jj) sacc[mi][t][jj] = 0.0f;

            #pragma unroll
            for (int d = 0; d < 4; ++d) {
                const uint2 qa0 = *(const uint2*)(Qs + (rbase + grp) * QS + 16 * d + 4 * c);
                const uint2 qb0 = *(const uint2*)(Qs + (rbase + 8 + grp) * QS + 16 * d + 4 * c);
                const uint2 qa1 = *(const uint2*)(Qs + (rbase + 16 + grp) * QS + 16 * d + 4 * c);
                const uint2 qb1 = *(const uint2*)(Qs + (rbase + 24 + grp) * QS + 16 * d + 4 * c);
                #pragma unroll
                for (int t = 0; t < 4; ++t) {
                    if (t > tcap) break;
                    const uint2 kf = *(const uint2*)
                        (Kt + (cb0 + 8 * t + grp) * QS + 16 * d + 4 * c);
                    mma16(sacc[0][t], qa0.x, qb0.x, qa0.y, qb0.y, kf.x, kf.y);
                    mma16(sacc[1][t], qa1.x, qb1.x, qa1.y, qb1.y, kf.x, kf.y);
                }
            }

            // ---- epilogue: f(s), mask, z, pack ----
            uint32_t pr[2][4][2];
            #pragma unroll
            for (int mi = 0; mi < 2; ++mi)
                #pragma unroll
                for (int t = 0; t < 4; ++t) { pr[mi][t][0] = 0u; pr[mi][t][1] = 0u; }
            #pragma unroll
            for (int mi = 0; mi < 2; ++mi) {
                const int rg0 = qbase + rbase + 16 * mi + grp;
                #pragma unroll
                for (int t = 0; t < 4; ++t) {
                    if (t > tcap) break;
                    const int cb = kbase + cb0 + 8 * t + 2 * c;
                    float s0 = sacc[mi][t][0], s1 = sacc[mi][t][1];
                    float s2 = sacc[mi][t][2], s3 = sacc[mi][t][3];
                    float p0 = fmaf(fmaf(0.5f, s0, 1.0f), s0, 1.0f);
                    float p1 = fmaf(fmaf(0.5f, s1, 1.0f), s1, 1.0f);
                    float p2 = fmaf(fmaf(0.5f, s2, 1.0f), s2, 1.0f);
                    float p3 = fmaf(fmaf(0.5f, s3, 1.0f), s3, 1.0f);
                    if (diag) {
                        if (cb     > rg0)     p0 = 0.0f;
                        if (cb + 1 > rg0)     p1 = 0.0f;
                        if (cb     > rg0 + 8) p2 = 0.0f;
                        if (cb + 1 > rg0 + 8) p3 = 0.0f;
                    }
                    zr[mi][0] += p0 + p1;
                    zr[mi][1] += p2 + p3;
                    pr[mi][t][0] = packh2(p0, p1);
                    pr[mi][t][1] = packh2(p2, p3);
                }
            }

            // ---- MMA2: O += P @ V ; A-frag = C-frags of tiles 2u,2u+1 ----
            #pragma unroll
            for (int u = 0; u < 2; ++u) {
                if (diag && cb0 + 16 * u > rbase + 31) break;
                const int vcol = 16 * (4 * nw + 2 * ch + u) + 4 * c;
                #pragma unroll
                for (int tn = 0; tn < 8; ++tn) {
                    const uint2 vf = *(const uint2*)
                        (Vtb + (8 * tn + grp) * VTS + vcol);
                    mma16(oacc[0][tn], pr[0][2 * u][0], pr[0][2 * u][1],
                          pr[0][2 * u + 1][0], pr[0][2 * u + 1][1], vf.x, vf.y);
                    mma16(oacc[1][tn], pr[1][2 * u][0], pr[1][2 * u][1],
                          pr[1][2 * u + 1][0], pr[1][2 * u + 1][1], vf.x, vf.y);
                }
            }
        }
        __syncthreads();
    }

    // ---- z lane-reduce over the 4 c-lanes ----
    #pragma unroll
    for (int mi = 0; mi < 2; ++mi) {
        zr[mi][0] += __shfl_xor_sync(0xffffffffu, zr[mi][0], 1);
        zr[mi][0] += __shfl_xor_sync(0xffffffffu, zr[mi][0], 2);
        zr[mi][1] += __shfl_xor_sync(0xffffffffu, zr[mi][1], 1);
        zr[mi][1] += __shfl_xor_sync(0xffffffffu, zr[mi][1], 2);
    }

    // ---- cross-col-group reduction via smem (reuse K/V buffer space) ----
    float* Osum = (float*)(smh + BM * QS);             // 4 x [32][OS] floats
    float* Zsum = (float*)(smh + BM * QS + 2 * BN * QS);  // 128 floats

    if (nw == 1) {
        float* base = Osum + mw * 32 * OS;
        #pragma unroll
        for (int mi = 0; mi < 2; ++mi) {
            const int r0 = 16 * mi + grp;
            #pragma unroll
            for (int tn = 0; tn < 8; ++tn) {
                *(float2*)(base + r0 * OS + 8 * tn + 2 * c) =
                    make_float2(oacc[mi][tn][0], oacc[mi][tn][1]);
                *(float2*)(base + (r0 + 8) * OS + 8 * tn + 2 * c) =
                    make_float2(oacc[mi][tn][2], oacc[mi][tn][3]);
            }
            if (c == 0) {
                Zsum[rbase + 16 * mi + grp]     = zr[mi][0];
                Zsum[rbase + 16 * mi + grp + 8] = zr[mi][1];
            }
        }
    }
    __syncthreads();

    if (nw == 0) {
        float* base = Osum + mw * 32 * OS;
        #pragma unroll
        for (int mi = 0; mi < 2; ++mi) {
            const int r0 = 16 * mi + grp;
            const float z0 = zr[mi][0] + Zsum[rbase + r0];
            const float z1 = zr[mi][1] + Zsum[rbase + r0 + 8];
            const float inv0 = 1.0f / (z0 + 1e-6f);
            const float inv1 = 1.0f / (z1 + 1e-6f);
            float* ob0 = O + (size_t)bh * L_SEQ * DHEAD
                       + (size_t)(qbase + rbase + r0) * DHEAD + 2 * c;
            float* ob1 = ob0 + 8 * DHEAD;
            #pragma unroll
            for (int tn = 0; tn < 8; ++tn) {
                const float2 s0 = *(const float2*)(base + r0 * OS + 8 * tn + 2 * c);
                const float2 s1 = *(const float2*)(base + (r0 + 8) * OS + 8 * tn + 2 * c);
                float2 w0, w1;
                w0.x = (oacc[mi][tn][0] + s0.x) * inv0;
                w0.y = (oacc[mi][tn][1] + s0.y) * inv0;
                w1.x = (oacc[mi][tn][2] + s1.x) * inv1;
                w1.y = (oacc[mi][tn][3] + s1.y) * inv1;
                *(float2*)(ob0 + 8 * tn) = w0;
                *(float2*)(ob1 + 8 * tn) = w1;
            }
        }
    }
}

extern "C" void kernel_launch(void* const* d_in, const int* in_sizes, int n_in,
                              void* d_out, int out_size) {
    (void)in_sizes; (void)n_in; (void)out_size;
    const float* q = (const float*)d_in[0];
    const float* k = (const float*)d_in[1];
    const float* v = (const float*)d_in[2];
    float* o = (float*)d_out;

    const int smem_bytes = (BM * QS + 2 * BN * QS + 2 * 64 * VTS) * 2;  // 90112 B
    static bool configured = false;
    if (!configured) {
        cudaFuncSetAttribute(taylor_attn_h,
                             cudaFuncAttributeMaxDynamicSharedMemorySize, smem_bytes);
        configured = true;
    }

    prep_all<<<dim3(1024, 2), 256>>>(q, k, v);

    dim3 grid((L_SEQ / BM) * NBH);   // 512, global LPT order
    taylor_attn_h<<<grid, 256, smem_bytes>>>(o);
}

// round 10
// speedup vs baseline: 7.2560x; 1.0169x over previous
#include <cuda_runtime.h>
#include <cuda_fp16.h>
#include <cstdint>

// Taylor causal attention, fp16 mma.sync m16n8k16 (fp32 accum).
// Persistent CTAs + dynamic LPT work queue; 2-D warp tiling (4x2);
// cp.async double-buffered; diag skipping.
// B=2,H=16,L=2048,D=64. Tile: 128 q-rows, k-tiles of 128.

#define L_SEQ 2048
#define DHEAD 64
#define NBH   32
#define BM    128
#define BN    128
#define QS    72     // Q/K smem row stride in halves (144B; deg-2 banks)
#define VTS   136    // Vt smem row stride in halves (272B; deg-2 banks)
#define OS    66     // O-partial reduction row stride (floats)
#define NTILES 512
#define SMEM_MAIN ((BM * QS + 2 * BN * QS + 2 * 64 * VTS) * 2)   // 90112 B

__device__ __align__(16) __half g_Qh[NBH * L_SEQ * DHEAD];  // scaled, interleaved
__device__ __align__(16) __half g_Kh[NBH * L_SEQ * DHEAD];  // interleaved
__device__ __align__(16) __half g_Vth[NBH * DHEAD * L_SEQ]; // [d][k], k-interleaved
__device__ int g_ctr;                                        // work-queue cursor

static __device__ __forceinline__ uint32_t packh2(float lo, float hi) {
    __half2 h = __floats2half2_rn(lo, hi);
    return *(uint32_t*)&h;
}
static __device__ __forceinline__ uint32_t smem_u32(const void* p) {
    uint32_t a;
    asm("{ .reg .u64 t; cvta.to.shared.u64 t, %1; cvt.u32.u64 %0, t; }" : "=r"(a) : "l"(p));
    return a;
}
static __device__ __forceinline__ void cp16(uint32_t s, const void* g) {
    asm volatile("cp.async.cg.shared.global [%0], [%1], 16;"
                 :: "r"(s), "l"(__cvta_generic_to_global(g)));
}
static __device__ __forceinline__ void cp_commit() {
    asm volatile("cp.async.commit_group;" ::: "memory");
}
static __device__ __forceinline__ void cp_wait1() {
    asm volatile("cp.async.wait_group 1;" ::: "memory");
}
static __device__ __forceinline__ void cp_wait0() {
    asm volatile("cp.async.wait_group 0;" ::: "memory");
}
static __device__ __forceinline__ void mma16(float* d,
        uint32_t a0, uint32_t a1, uint32_t a2, uint32_t a3,
        uint32_t b0, uint32_t b1) {
    asm volatile(
        "mma.sync.aligned.m16n8k16.row.col.f32.f16.f16.f32 "
        "{%0,%1,%2,%3}, {%4,%5,%6,%7}, {%8,%9}, {%0,%1,%2,%3};"
        : "+f"(d[0]), "+f"(d[1]), "+f"(d[2]), "+f"(d[3])
        : "r"(a0), "r"(a1), "r"(a2), "r"(a3), "r"(b0), "r"(b1));
}

// ---- merged prep: y=0 -> Q,K convert+interleave; y=1 -> V transpose ----
__global__ void __launch_bounds__(256)
prep_all(const float* __restrict__ Q, const float* __restrict__ K,
         const float* __restrict__ V)
{
    if (blockIdx.x == 0 && blockIdx.y == 0 && threadIdx.x == 0) g_ctr = 0;

    if (blockIdx.y == 0) {
        const int g   = blockIdx.x * 256 + threadIdx.x;
        const size_t off = (size_t)(g >> 2) * DHEAD + ((g & 3) << 4);

        float4 f0 = *(const float4*)(Q + off);
        float4 f1 = *(const float4*)(Q + off + 4);
        float4 f2 = *(const float4*)(Q + off + 8);
        float4 f3 = *(const float4*)(Q + off + 12);
        uint4 a, b;
        a.x = packh2(f0.x * 0.125f, f0.y * 0.125f);
        a.y = packh2(f2.x * 0.125f, f2.y * 0.125f);
        a.z = packh2(f0.z * 0.125f, f0.w * 0.125f);
        a.w = packh2(f2.z * 0.125f, f2.w * 0.125f);
        b.x = packh2(f1.x * 0.125f, f1.y * 0.125f);
        b.y = packh2(f3.x * 0.125f, f3.y * 0.125f);
        b.z = packh2(f1.z * 0.125f, f1.w * 0.125f);
        b.w = packh2(f3.z * 0.125f, f3.w * 0.125f);
        *(uint4*)(g_Qh + off)     = a;
        *(uint4*)(g_Qh + off + 8) = b;

        f0 = *(const float4*)(K + off);
        f1 = *(const float4*)(K + off + 4);
        f2 = *(const float4*)(K + off + 8);
        f3 = *(const float4*)(K + off + 12);
        a.x = packh2(f0.x, f0.y);  a.y = packh2(f2.x, f2.y);
        a.z = packh2(f0.z, f0.w);  a.w = packh2(f2.z, f2.w);
        b.x = packh2(f1.x, f1.y);  b.y = packh2(f3.x, f3.y);
        b.z = packh2(f1.z, f1.w);  b.w = packh2(f3.z, f3.w);
        *(uint4*)(g_Kh + off)     = a;
        *(uint4*)(g_Kh + off + 8) = b;
    } else {
        __shared__ float ts[64][68];
        const int tid = threadIdx.x;
        const int kt0 = (blockIdx.x & 31) * 64;
        const int bh  = blockIdx.x >> 5;
        const float* vsrc = V + (size_t)bh * L_SEQ * DHEAD;
        __half* vdst = g_Vth + (size_t)bh * DHEAD * L_SEQ;

        #pragma unroll
        for (int i = 0; i < 4; ++i) {
            const int idx = tid + 256 * i;
            const int row = idx >> 4, c4 = (idx & 15) << 2;
            *(float4*)&ts[row][c4] =
                *(const float4*)(vsrc + (size_t)(kt0 + row) * DHEAD + c4);
        }
        __syncthreads();

        const int d  = tid >> 2;
        const int kb = (tid & 3) << 4;
        uint4 a, b;
        a.x = packh2(ts[kb + 0][d],  ts[kb + 1][d]);
        a.y = packh2(ts[kb + 8][d],  ts[kb + 9][d]);
        a.z = packh2(ts[kb + 2][d],  ts[kb + 3][d]);
        a.w = packh2(ts[kb + 10][d], ts[kb + 11][d]);
        b.x = packh2(ts[kb + 4][d],  ts[kb + 5][d]);
        b.y = packh2(ts[kb + 12][d], ts[kb + 13][d]);
        b.z = packh2(ts[kb + 6][d],  ts[kb + 7][d]);
        b.w = packh2(ts[kb + 14][d], ts[kb + 15][d]);
        __half* dst = vdst + (size_t)d * L_SEQ + kt0 + kb;
        *(uint4*)dst       = a;
        *(uint4*)(dst + 8) = b;
    }
}

// ---- main kernel: persistent CTAs over a dynamic LPT work list ----
__global__ void __launch_bounds__(256, 2)
taylor_attn_h(float* __restrict__ O)
{
    extern __shared__ __half smh[];
    __half* Qs = smh;                      // [128][72]
    __half* Kb = Qs + BM * QS;             // [2][128][72]
    __half* Vb = Kb + 2 * BN * QS;         // [2][64][136]
    int* wptr  = (int*)((char*)smh + SMEM_MAIN);   // work-index broadcast
    const uint32_t sQs = smem_u32(Qs);
    const uint32_t sKb = smem_u32(Kb);
    const uint32_t sVb = smem_u32(Vb);

    const int tid  = threadIdx.x;
    const int wid  = tid >> 5;
    const int lane = tid & 31;
    const int grp  = lane >> 2;
    const int c    = lane & 3;
    const int mw   = wid & 3;              // row group (32 rows)
    const int nw   = wid >> 2;             // col group (64 cols)
    const int rbase = 32 * mw;
    const int colw  = 64 * nw;

    for (;;) {
        if (tid == 0) *wptr = atomicAdd(&g_ctr, 1);
        __syncthreads();
        const int widx = *wptr;
        if (widx >= NTILES) break;

        // LPT order: biggest q-tiles first across all heads
        const int qt = (L_SEQ / BM) - 1 - (widx >> 5);
        const int bh = widx & 31;
        const int qbase = qt * BM;

        const __half* Qg = g_Qh + (size_t)bh * L_SEQ * DHEAD;
        const __half* Kg = g_Kh + (size_t)bh * L_SEQ * DHEAD;
        const __half* Vg = g_Vth + (size_t)bh * DHEAD * L_SEQ;

        // ---- prologue: Q tile + K/V tile 0 ----
        #pragma unroll
        for (int i = 0; i < 4; ++i) {
            const int idx = tid + 256 * i;
            const int row = idx >> 3, ch = idx & 7;
            cp16(sQs + (uint32_t)(row * QS + ch * 8) * 2,
                 Qg + (size_t)(qbase + row) * DHEAD + ch * 8);
            cp16(sKb + (uint32_t)(row * QS + ch * 8) * 2,
                 Kg + (size_t)row * DHEAD + ch * 8);
        }
        #pragma unroll
        for (int i = 0; i < 4; ++i) {
            const int idx = tid + 256 * i;
            const int row = idx >> 4, ch = idx & 15;
            cp16(sVb + (uint32_t)(row * VTS + ch * 8) * 2,
                 Vg + (size_t)row * L_SEQ + ch * 8);
        }
        cp_commit();

        float oacc[2][8][4];
        #pragma unroll
        for (int mi = 0; mi < 2; ++mi)
            #pragma unroll
            for (int t = 0; t < 8; ++t)
                #pragma unroll
                for (int j = 0; j < 4; ++j) oacc[mi][t][j] = 0.0f;
        float zr[2][2] = {};

        for (int j = 0; j <= qt; ++j) {
            const int buf = j & 1;

            if (j < qt) {   // prefetch tile j+1
                const int nb = buf ^ 1;
                const int kb1 = (j + 1) * BN;
                const uint32_t dK = sKb + (uint32_t)(nb * BN * QS) * 2;
                const uint32_t dV = sVb + (uint32_t)(nb * 64 * VTS) * 2;
                #pragma unroll
                for (int i = 0; i < 4; ++i) {
                    const int idx = tid + 256 * i;
                    const int rowk = idx >> 3, chk = idx & 7;
                    cp16(dK + (uint32_t)(rowk * QS + chk * 8) * 2,
                         Kg + (size_t)(kb1 + rowk) * DHEAD + chk * 8);
                    const int rowv = idx >> 4, chv = idx & 15;
                    cp16(dV + (uint32_t)(rowv * VTS + chv * 8) * 2,
                         Vg + (size_t)rowv * L_SEQ + kb1 + chv * 8);
                }
                cp_commit();
                cp_wait1();
            } else {
                cp_wait0();
            }
            __syncthreads();

            const __half* Kt  = Kb + buf * BN * QS;
            const __half* Vtb = Vb + buf * 64 * VTS;
            const int kbase = j * BN;
            const bool diag = (j == qt);

            #pragma unroll
            for (int ch = 0; ch < 2; ++ch) {     // warp's two 32-col chunks
                const int cb0 = colw + 32 * ch;
                if (diag && cb0 > rbase + 31) continue;
                const int tcap = diag ? ((rbase + 31 - cb0) >> 3) : 3;

                // ---- MMA1: S chunk (32 x 32) = Q @ K^T ----
                float sacc[2][4][4];
                #pragma unroll
                for (int mi = 0; mi < 2; ++mi)
                    #pragma unroll
                    for (int t = 0; t < 4; ++t)
                        #pragma unroll
                        for (int jj = 0; jj < 4; ++jj) sacc[mi][t][jj] = 0.0f;

                #pragma unroll
                for (int d = 0; d < 4; ++d) {
                    const uint2 qa0 = *(const uint2*)(Qs + (rbase + grp) * QS + 16 * d + 4 * c);
                    const uint2 qb0 = *(const uint2*)(Qs + (rbase + 8 + grp) * QS + 16 * d + 4 * c);
                    const uint2 qa1 = *(const uint2*)(Qs + (rbase + 16 + grp) * QS + 16 * d + 4 * c);
                    const uint2 qb1 = *(const uint2*)(Qs + (rbase + 24 + grp) * QS + 16 * d + 4 * c);
                    #pragma unroll
                    for (int t = 0; t < 4; ++t) {
                        if (t > tcap) break;
                        const uint2 kf = *(const uint2*)
                            (Kt + (cb0 + 8 * t + grp) * QS + 16 * d + 4 * c);
                        mma16(sacc[0][t], qa0.x, qb0.x, qa0.y, qb0.y, kf.x, kf.y);
                        mma16(sacc[1][t], qa1.x, qb1.x, qa1.y, qb1.y, kf.x, kf.y);
                    }
                }

                // ---- epilogue: f(s), mask, z, pack ----
                uint32_t pr[2][4][2];
                #pragma unroll
                for (int mi = 0; mi < 2; ++mi)
                    #pragma unroll
                    for (int t = 0; t < 4; ++t) { pr[mi][t][0] = 0u; pr[mi][t][1] = 0u; }
                #pragma unroll
                for (int mi = 0; mi < 2; ++mi) {
                    const int rg0 = qbase + rbase + 16 * mi + grp;
                    #pragma unroll
                    for (int t = 0; t < 4; ++t) {
                        if (t > tcap) break;
                        const int cb = kbase + cb0 + 8 * t + 2 * c;
                        float s0 = sacc[mi][t][0], s1 = sacc[mi][t][1];
                        float s2 = sacc[mi][t][2], s3 = sacc[mi][t][3];
                        float p0 = fmaf(fmaf(0.5f, s0, 1.0f), s0, 1.0f);
                        float p1 = fmaf(fmaf(0.5f, s1, 1.0f), s1, 1.0f);
                        float p2 = fmaf(fmaf(0.5f, s2, 1.0f), s2, 1.0f);
                        float p3 = fmaf(fmaf(0.5f, s3, 1.0f), s3, 1.0f);
                        if (diag) {
                            if (cb     > rg0)     p0 = 0.0f;
                            if (cb + 1 > rg0)     p1 = 0.0f;
                            if (cb     > rg0 + 8) p2 = 0.0f;
                            if (cb + 1 > rg0 + 8) p3 = 0.0f;
                        }
                        zr[mi][0] += p0 + p1;
                        zr[mi][1] += p2 + p3;
                        pr[mi][t][0] = packh2(p0, p1);
                        pr[mi][t][1] = packh2(p2, p3);
                    }
                }

                // ---- MMA2: O += P @ V ----
                #pragma unroll
                for (int u = 0; u < 2; ++u) {
                    if (diag && cb0 + 16 * u > rbase + 31) break;
                    const int vcol = 16 * (4 * nw + 2 * ch + u) + 4 * c;
                    #pragma unroll
                    for (int tn = 0; tn < 8; ++tn) {
                        const uint2 vf = *(const uint2*)
                            (Vtb + (8 * tn + grp) * VTS + vcol);
                        mma16(oacc[0][tn], pr[0][2 * u][0], pr[0][2 * u][1],
                              pr[0][2 * u + 1][0], pr[0][2 * u + 1][1], vf.x, vf.y);
                        mma16(oacc[1][tn], pr[1][2 * u][0], pr[1][2 * u][1],
                              pr[1][2 * u + 1][0], pr[1][2 * u + 1][1], vf.x, vf.y);
                    }
                }
            }
            __syncthreads();
        }

        // ---- z lane-reduce over the 4 c-lanes ----
        #pragma unroll
        for (int mi = 0; mi < 2; ++mi) {
            zr[mi][0] += __shfl_xor_sync(0xffffffffu, zr[mi][0], 1);
            zr[mi][0] += __shfl_xor_sync(0xffffffffu, zr[mi][0], 2);
            zr[mi][1] += __shfl_xor_sync(0xffffffffu, zr[mi][1], 1);
            zr[mi][1] += __shfl_xor_sync(0xffffffffu, zr[mi][1], 2);
        }

        // ---- cross-col-group reduction via smem (reuse K/V buffer space) ----
        float* Osum = (float*)(smh + BM * QS);
        float* Zsum = (float*)(smh + BM * QS + 2 * BN * QS);

        if (nw == 1) {
            float* base = Osum + mw * 32 * OS;
            #pragma unroll
            for (int mi = 0; mi < 2; ++mi) {
                const int r0 = 16 * mi + grp;
                #pragma unroll
                for (int tn = 0; tn < 8; ++tn) {
                    *(float2*)(base + r0 * OS + 8 * tn + 2 * c) =
                        make_float2(oacc[mi][tn][0], oacc[mi][tn][1]);
                    *(float2*)(base + (r0 + 8) * OS + 8 * tn + 2 * c) =
                        make_float2(oacc[mi][tn][2], oacc[mi][tn][3]);
                }
                if (c == 0) {
                    Zsum[rbase + 16 * mi + grp]     = zr[mi][0];
                    Zsum[rbase + 16 * mi + grp + 8] = zr[mi][1];
                }
            }
        }
        __syncthreads();

        if (nw == 0) {
            float* base = Osum + mw * 32 * OS;
            #pragma unroll
            for (int mi = 0; mi < 2; ++mi) {
                const int r0 = 16 * mi + grp;
                const float z0 = zr[mi][0] + Zsum[rbase + r0];
                const float z1 = zr[mi][1] + Zsum[rbase + r0 + 8];
                const float inv0 = 1.0f / (z0 + 1e-6f);
                const float inv1 = 1.0f / (z1 + 1e-6f);
                float* ob0 = O + (size_t)bh * L_SEQ * DHEAD
                           + (size_t)(qbase + rbase + r0) * DHEAD + 2 * c;
                float* ob1 = ob0 + 8 * DHEAD;
                #pragma unroll
                for (int tn = 0; tn < 8; ++tn) {
                    const float2 s0 = *(const float2*)(base + r0 * OS + 8 * tn + 2 * c);
                    const float2 s1 = *(const float2*)(base + (r0 + 8) * OS + 8 * tn + 2 * c);
                    float2 w0, w1;
                    w0.x = (oacc[mi][tn][0] + s0.x) * inv0;
                    w0.y = (oacc[mi][tn][1] + s0.y) * inv0;
                    w1.x = (oacc[mi][tn][2] + s1.x) * inv1;
                    w1.y = (oacc[mi][tn][3] + s1.y) * inv1;
                    *(float2*)(ob0 + 8 * tn) = w0;
                    *(float2*)(ob1 + 8 * tn) = w1;
                }
            }
        }
        __syncthreads();   // Osum readers done before next tile's prefetch
    }
}

extern "C" void kernel_launch(void* const* d_in, const int* in_sizes, int n_in,
                              void* d_out, int out_size) {
    (void)in_sizes; (void)n_in; (void)out_size;
    const float* q = (const float*)d_in[0];
    const float* k = (const float*)d_in[1];
    const float* v = (const float*)d_in[2];
    float* o = (float*)d_out;

    const int smem_bytes = SMEM_MAIN + 16;   // + work-index broadcast slot
    static bool configured = false;
    if (!configured) {
        cudaFuncSetAttribute(taylor_attn_h,
                             cudaFuncAttributeMaxDynamicSharedMemorySize, smem_bytes);
        configured = true;
    }

    prep_all<<<dim3(1024, 2), 256>>>(q, k, v);

    taylor_attn_h<<<304, 256, smem_bytes>>>(o);   // persistent: 2 CTAs x 152 SMs
}

// round 11
// speedup vs baseline: 7.4588x; 1.0279x over previous
#include <cuda_runtime.h>
#include <cuda_fp16.h>
#include <cstdint>

// Taylor causal attention, fp16 mma.sync m16n8k16 (fp32 accum).
// Persistent CTAs + dynamic LPT queue; 2-D warp tiling (4 row x 2 col groups);
// Q fragments register-resident across the whole k-loop; 16-col chunks;
// single barrier per k-tile; diag/non-diag specialized paths.
// B=2,H=16,L=2048,D=64. Tile: 128 q-rows, k-tiles of 128.

#define L_SEQ 2048
#define DHEAD 64
#define NBH   32
#define BM    128
#define BN    128
#define QS    72     // Q/K smem row stride in halves (144B; deg-2 banks)
#define VTS   136    // Vt smem row stride in halves (272B; deg-2 banks)
#define OS    66     // O-partial reduction row stride (floats)
#define NTILES 512
#define SMEM_MAIN ((BM * QS + 2 * BN * QS + 2 * 64 * VTS) * 2)   // 90112 B

__device__ __align__(16) __half g_Qh[NBH * L_SEQ * DHEAD];  // scaled, interleaved
__device__ __align__(16) __half g_Kh[NBH * L_SEQ * DHEAD];  // interleaved
__device__ __align__(16) __half g_Vth[NBH * DHEAD * L_SEQ]; // [d][k], k-interleaved
__device__ int g_ctr;                                        // work-queue cursor

static __device__ __forceinline__ uint32_t packh2(float lo, float hi) {
    __half2 h = __floats2half2_rn(lo, hi);
    return *(uint32_t*)&h;
}
static __device__ __forceinline__ uint32_t smem_u32(const void* p) {
    uint32_t a;
    asm("{ .reg .u64 t; cvta.to.shared.u64 t, %1; cvt.u32.u64 %0, t; }" : "=r"(a) : "l"(p));
    return a;
}
static __device__ __forceinline__ void cp16(uint32_t s, const void* g) {
    asm volatile("cp.async.cg.shared.global [%0], [%1], 16;"
                 :: "r"(s), "l"(__cvta_generic_to_global(g)));
}
static __device__ __forceinline__ void cp_commit() {
    asm volatile("cp.async.commit_group;" ::: "memory");
}
static __device__ __forceinline__ void cp_wait0() {
    asm volatile("cp.async.wait_group 0;" ::: "memory");
}
static __device__ __forceinline__ void mma16(float* d,
        uint32_t a0, uint32_t a1, uint32_t a2, uint32_t a3,
        uint32_t b0, uint32_t b1) {
    asm volatile(
        "mma.sync.aligned.m16n8k16.row.col.f32.f16.f16.f32 "
        "{%0,%1,%2,%3}, {%4,%5,%6,%7}, {%8,%9}, {%0,%1,%2,%3};"
        : "+f"(d[0]), "+f"(d[1]), "+f"(d[2]), "+f"(d[3])
        : "r"(a0), "r"(a1), "r"(a2), "r"(a3), "r"(b0), "r"(b1));
}

// ---- merged prep: y=0 -> Q,K convert+interleave; y=1 -> V transpose ----
__global__ void __launch_bounds__(256)
prep_all(const float* __restrict__ Q, const float* __restrict__ K,
         const float* __restrict__ V)
{
    if (blockIdx.x == 0 && blockIdx.y == 0 && threadIdx.x == 0) g_ctr = 0;

    if (blockIdx.y == 0) {
        const int g   = blockIdx.x * 256 + threadIdx.x;
        const size_t off = (size_t)(g >> 2) * DHEAD + ((g & 3) << 4);

        float4 f0 = *(const float4*)(Q + off);
        float4 f1 = *(const float4*)(Q + off + 4);
        float4 f2 = *(const float4*)(Q + off + 8);
        float4 f3 = *(const float4*)(Q + off + 12);
        uint4 a, b;
        a.x = packh2(f0.x * 0.125f, f0.y * 0.125f);
        a.y = packh2(f2.x * 0.125f, f2.y * 0.125f);
        a.z = packh2(f0.z * 0.125f, f0.w * 0.125f);
        a.w = packh2(f2.z * 0.125f, f2.w * 0.125f);
        b.x = packh2(f1.x * 0.125f, f1.y * 0.125f);
        b.y = packh2(f3.x * 0.125f, f3.y * 0.125f);
        b.z = packh2(f1.z * 0.125f, f1.w * 0.125f);
        b.w = packh2(f3.z * 0.125f, f3.w * 0.125f);
        *(uint4*)(g_Qh + off)     = a;
        *(uint4*)(g_Qh + off + 8) = b;

        f0 = *(const float4*)(K + off);
        f1 = *(const float4*)(K + off + 4);
        f2 = *(const float4*)(K + off + 8);
        f3 = *(const float4*)(K + off + 12);
        a.x = packh2(f0.x, f0.y);  a.y = packh2(f2.x, f2.y);
        a.z = packh2(f0.z, f0.w);  a.w = packh2(f2.z, f2.w);
        b.x = packh2(f1.x, f1.y);  b.y = packh2(f3.x, f3.y);
        b.z = packh2(f1.z, f1.w);  b.w = packh2(f3.z, f3.w);
        *(uint4*)(g_Kh + off)     = a;
        *(uint4*)(g_Kh + off + 8) = b;
    } else {
        __shared__ float ts[64][68];
        const int tid = threadIdx.x;
        const int kt0 = (blockIdx.x & 31) * 64;
        const int bh  = blockIdx.x >> 5;
        const float* vsrc = V + (size_t)bh * L_SEQ * DHEAD;
        __half* vdst = g_Vth + (size_t)bh * DHEAD * L_SEQ;

        #pragma unroll
        for (int i = 0; i < 4; ++i) {
            const int idx = tid + 256 * i;
            const int row = idx >> 4, c4 = (idx & 15) << 2;
            *(float4*)&ts[row][c4] =
                *(const float4*)(vsrc + (size_t)(kt0 + row) * DHEAD + c4);
        }
        __syncthreads();

        const int d  = tid >> 2;
        const int kb = (tid & 3) << 4;
        uint4 a, b;
        a.x = packh2(ts[kb + 0][d],  ts[kb + 1][d]);
        a.y = packh2(ts[kb + 8][d],  ts[kb + 9][d]);
        a.z = packh2(ts[kb + 2][d],  ts[kb + 3][d]);
        a.w = packh2(ts[kb + 10][d], ts[kb + 11][d]);
        b.x = packh2(ts[kb + 4][d],  ts[kb + 5][d]);
        b.y = packh2(ts[kb + 12][d], ts[kb + 13][d]);
        b.z = packh2(ts[kb + 6][d],  ts[kb + 7][d]);
        b.w = packh2(ts[kb + 14][d], ts[kb + 15][d]);
        __half* dst = vdst + (size_t)d * L_SEQ + kt0 + kb;
        *(uint4*)dst       = a;
        *(uint4*)(dst + 8) = b;
    }
}

// ---- one k-tile of compute for one warp (4 chunks of 16 cols) ----
template<bool DIAG>
static __device__ __forceinline__ void tile_step(
    const __half* __restrict__ Kt, const __half* __restrict__ Vtb,
    const uint32_t (&qf)[2][4][4],
    float (&oacc)[2][8][4], float (&zr)[2][2],
    int colw, int rbase, int grp, int c)
{
    #pragma unroll
    for (int ch = 0; ch < 4; ++ch) {
        const int cb0 = colw + 16 * ch;           // chunk column base (local)
        if (DIAG && cb0 > rbase + 31) break;      // fully above all warp rows
        const int tcap = DIAG ? (((rbase + 31 - cb0) >> 3) ? 1 : 0) : 1;

        // ---- MMA1: S chunk (32 rows x 16 cols) = Q @ K^T ----
        float sacc[2][2][4];
        #pragma unroll
        for (int mi = 0; mi < 2; ++mi)
            #pragma unroll
            for (int t = 0; t < 2; ++t)
                #pragma unroll
                for (int jj = 0; jj < 4; ++jj) sacc[mi][t][jj] = 0.0f;

        #pragma unroll
        for (int d = 0; d < 4; ++d) {
            #pragma unroll
            for (int t = 0; t < 2; ++t) {
                if (DIAG && t > tcap) continue;
                const uint2 kf = *(const uint2*)
                    (Kt + (cb0 + 8 * t + grp) * QS + 16 * d + 4 * c);
                mma16(sacc[0][t], qf[0][d][0], qf[0][d][1], qf[0][d][2], qf[0][d][3],
                      kf.x, kf.y);
                mma16(sacc[1][t], qf[1][d][0], qf[1][d][1], qf[1][d][2], qf[1][d][3],
                      kf.x, kf.y);
            }
        }

        // ---- epilogue: f(s), mask, z, pack ----
        uint32_t pr[2][2][2];
        #pragma unroll
        for (int mi = 0; mi < 2; ++mi)
            #pragma unroll
            for (int t = 0; t < 2; ++t) { pr[mi][t][0] = 0u; pr[mi][t][1] = 0u; }
        #pragma unroll
        for (int mi = 0; mi < 2; ++mi) {
            const int r0 = rbase + 16 * mi + grp;     // local row of p0/p1
            #pragma unroll
            for (int t = 0; t < 2; ++t) {
                if (DIAG && t > tcap) continue;
                const int cb = cb0 + 8 * t + 2 * c;   // local col of p0/p2
                float s0 = sacc[mi][t][0], s1 = sacc[mi][t][1];
                float s2 = sacc[mi][t][2], s3 = sacc[mi][t][3];
                float p0 = fmaf(fmaf(0.5f, s0, 1.0f), s0, 1.0f);
                float p1 = fmaf(fmaf(0.5f, s1, 1.0f), s1, 1.0f);
                float p2 = fmaf(fmaf(0.5f, s2, 1.0f), s2, 1.0f);
                float p3 = fmaf(fmaf(0.5f, s3, 1.0f), s3, 1.0f);
                if (DIAG) {
                    if (cb     > r0)     p0 = 0.0f;
                    if (cb + 1 > r0)     p1 = 0.0f;
                    if (cb     > r0 + 8) p2 = 0.0f;
                    if (cb + 1 > r0 + 8) p3 = 0.0f;
                }
                zr[mi][0] += p0 + p1;
                zr[mi][1] += p2 + p3;
                pr[mi][t][0] = packh2(p0, p1);
                pr[mi][t][1] = packh2(p2, p3);
            }
        }

        // ---- MMA2: O += P @ V (one 16-k block; A-frag = C-frags in-lane) ----
        const int vcol = cb0 + 4 * c;
        #pragma unroll
        for (int tn = 0; tn < 8; ++tn) {
            const uint2 vf = *(const uint2*)(Vtb + (8 * tn + grp) * VTS + vcol);
            mma16(oacc[0][tn], pr[0][0][0], pr[0][0][1], pr[0][1][0], pr[0][1][1],
                  vf.x, vf.y);
            mma16(oacc[1][tn], pr[1][0][0], pr[1][0][1], pr[1][1][0], pr[1][1][1],
                  vf.x, vf.y);
        }
    }
}

// ---- main kernel: persistent CTAs over a dynamic LPT work list ----
__global__ void __launch_bounds__(256, 2)
taylor_attn_h(float* __restrict__ O)
{
    extern __shared__ __half smh[];
    __half* Qs = smh;                      // [128][72]
    __half* Kb = Qs + BM * QS;             // [2][128][72]
    __half* Vb = Kb + 2 * BN * QS;         // [2][64][136]
    int* wptr  = (int*)((char*)smh + SMEM_MAIN);
    const uint32_t sQs = smem_u32(Qs);
    const uint32_t sKb = smem_u32(Kb);
    const uint32_t sVb = smem_u32(Vb);

    const int tid  = threadIdx.x;
    const int wid  = tid >> 5;
    const int lane = tid & 31;
    const int grp  = lane >> 2;
    const int c    = lane & 3;
    const int mw   = wid & 3;              // row group (32 rows)
    const int nw   = wid >> 2;             // col group (64 cols)
    const int rbase = 32 * mw;
    const int colw  = 64 * nw;

    for (;;) {
        if (tid == 0) *wptr = atomicAdd(&g_ctr, 1);
        __syncthreads();
        const int widx = *wptr;
        if (widx >= NTILES) break;

        const int qt = (L_SEQ / BM) - 1 - (widx >> 5);   // LPT: big first
        const int bh = widx & 31;
        const int qbase = qt * BM;

        const __half* Qg = g_Qh + (size_t)bh * L_SEQ * DHEAD;
        const __half* Kg = g_Kh + (size_t)bh * L_SEQ * DHEAD;
        const __half* Vg = g_Vth + (size_t)bh * DHEAD * L_SEQ;

        // ---- prologue: Q tile + K/V tile 0 ----
        #pragma unroll
        for (int i = 0; i < 4; ++i) {
            const int idx = tid + 256 * i;
            const int row = idx >> 3, ch = idx & 7;
            cp16(sQs + (uint32_t)(row * QS + ch * 8) * 2,
                 Qg + (size_t)(qbase + row) * DHEAD + ch * 8);
            cp16(sKb + (uint32_t)(row * QS + ch * 8) * 2,
                 Kg + (size_t)row * DHEAD + ch * 8);
        }
        #pragma unroll
        for (int i = 0; i < 4; ++i) {
            const int idx = tid + 256 * i;
            const int row = idx >> 4, ch = idx & 15;
            cp16(sVb + (uint32_t)(row * VTS + ch * 8) * 2,
                 Vg + (size_t)row * L_SEQ + ch * 8);
        }
        cp_commit();
        cp_wait0();
        __syncthreads();

        // ---- Q fragments -> registers for the whole k-loop ----
        uint32_t qf[2][4][4];
        #pragma unroll
        for (int mi = 0; mi < 2; ++mi)
            #pragma unroll
            for (int d = 0; d < 4; ++d) {
                const uint2 qa = *(const uint2*)
                    (Qs + (rbase + 16 * mi + grp) * QS + 16 * d + 4 * c);
                const uint2 qb = *(const uint2*)
                    (Qs + (rbase + 16 * mi + 8 + grp) * QS + 16 * d + 4 * c);
                qf[mi][d][0] = qa.x; qf[mi][d][1] = qb.x;
                qf[mi][d][2] = qa.y; qf[mi][d][3] = qb.y;
            }

        float oacc[2][8][4];
        #pragma unroll
        for (int mi = 0; mi < 2; ++mi)
            #pragma unroll
            for (int t = 0; t < 8; ++t)
                #pragma unroll
                for (int j = 0; j < 4; ++j) oacc[mi][t][j] = 0.0f;
        float zr[2][2] = {};

        for (int j = 0; j <= qt; ++j) {
            const int buf = j & 1;

            if (j < qt) {   // prefetch tile j+1 into the other buffer
                const int nb = buf ^ 1;
                const int kb1 = (j + 1) * BN;
                const uint32_t dK = sKb + (uint32_t)(nb * BN * QS) * 2;
                const uint32_t dV = sVb + (uint32_t)(nb * 64 * VTS) * 2;
                #pragma unroll
                for (int i = 0; i < 4; ++i) {
                    const int idx = tid + 256 * i;
                    const int rowk = idx >> 3, chk = idx & 7;
                    cp16(dK + (uint32_t)(rowk * QS + chk * 8) * 2,
                         Kg + (size_t)(kb1 + rowk) * DHEAD + chk * 8);
                    const int rowv = idx >> 4, chv = idx & 15;
                    cp16(dV + (uint32_t)(rowv * VTS + chv * 8) * 2,
                         Vg + (size_t)rowv * L_SEQ + kb1 + chv * 8);
                }
                cp_commit();
            }

            const __half* Kt  = Kb + buf * BN * QS;
            const __half* Vtb = Vb + buf * 64 * VTS;
            if (j == qt)
                tile_step<true >(Kt, Vtb, qf, oacc, zr, colw, rbase, grp, c);
            else
                tile_step<false>(Kt, Vtb, qf, oacc, zr, colw, rbase, grp, c);

            if (j < qt) cp_wait0();
            __syncthreads();   // buf free + next tile visible to all warps
        }

        // ---- z lane-reduce over the 4 c-lanes ----
        #pragma unroll
        for (int mi = 0; mi < 2; ++mi) {
            zr[mi][0] += __shfl_xor_sync(0xffffffffu, zr[mi][0], 1);
            zr[mi][0] += __shfl_xor_sync(0xffffffffu, zr[mi][0], 2);
            zr[mi][1] += __shfl_xor_sync(0xffffffffu, zr[mi][1], 1);
            zr[mi][1] += __shfl_xor_sync(0xffffffffu, zr[mi][1], 2);
        }

        // ---- cross-col-group reduction via smem (reuse K/V buffer space) ----
        float* Osum = (float*)(smh + BM * QS);
        float* Zsum = (float*)(smh + BM * QS + 2 * BN * QS);

        if (nw == 1) {
            float* base = Osum + mw * 32 * OS;
            #pragma unroll
            for (int mi = 0; mi < 2; ++mi) {
                const int r0 = 16 * mi + grp;
                #pragma unroll
                for (int tn = 0; tn < 8; ++tn) {
                    *(float2*)(base + r0 * OS + 8 * tn + 2 * c) =
                        make_float2(oacc[mi][tn][0], oacc[mi][tn][1]);
                    *(float2*)(base + (r0 + 8) * OS + 8 * tn + 2 * c) =
                        make_float2(oacc[mi][tn][2], oacc[mi][tn][3]);
                }
                if (c == 0) {
                    Zsum[rbase + 16 * mi + grp]     = zr[mi][0];
                    Zsum[rbase + 16 * mi + grp + 8] = zr[mi][1];
                }
            }
        }
        __syncthreads();

        if (nw == 0) {
            float* base = Osum + mw * 32 * OS;
            #pragma unroll
            for (int mi = 0; mi < 2; ++mi) {
                const int r0 = 16 * mi + grp;
                const float z0 = zr[mi][0] + Zsum[rbase + r0];
                const float z1 = zr[mi][1] + Zsum[rbase + r0 + 8];
                const float inv0 = 1.0f / (z0 + 1e-6f);
                const float inv1 = 1.0f / (z1 + 1e-6f);
                float* ob0 = O + (size_t)bh * L_SEQ * DHEAD
                           + (size_t)(qbase + rbase + r0) * DHEAD + 2 * c;
                float* ob1 = ob0 + 8 * DHEAD;
                #pragma unroll
                for (int tn = 0; tn < 8; ++tn) {
                    const float2 s0 = *(const float2*)(base + r0 * OS + 8 * tn + 2 * c);
                    const float2 s1 = *(const float2*)(base + (r0 + 8) * OS + 8 * tn + 2 * c);
                    float2 w0, w1;
                    w0.x = (oacc[mi][tn][0] + s0.x) * inv0;
                    w0.y = (oacc[mi][tn][1] + s0.y) * inv0;
                    w1.x = (oacc[mi][tn][2] + s1.x) * inv1;
                    w1.y = (oacc[mi][tn][3] + s1.y) * inv1;
                    *(float2*)(ob0 + 8 * tn) = w0;
                    *(float2*)(ob1 + 8 * tn) = w1;
                }
            }
        }
        __syncthreads();   // Osum readers done before next tile's prologue
    }
}

extern "C" void kernel_launch(void* const* d_in, const int* in_sizes, int n_in,
                              void* d_out, int out_size) {
    (void)in_sizes; (void)n_in; (void)out_size;
    const float* q = (const float*)d_in[0];
    const float* k = (const float*)d_in[1];
    const float* v = (const float*)d_in[2];
    float* o = (float*)d_out;

    const int smem_bytes = SMEM_MAIN + 16;
    static bool configured = false;
    if (!configured) {
        cudaFuncSetAttribute(taylor_attn_h,
                             cudaFuncAttributeMaxDynamicSharedMemorySize, smem_bytes);
        configured = true;
    }

    prep_all<<<dim3(1024, 2), 256>>>(q, k, v);

    taylor_attn_h<<<304, 256, smem_bytes>>>(o);   // persistent: 2 CTAs x 152 SMs
}

// round 12
// speedup vs baseline: 7.9555x; 1.0666x over previous
#include <cuda_runtime.h>
#include <cuda_fp16.h>
#include <cstdint>

// Taylor causal attention, fp16 mma.sync m16n8k16 (fp32 accum).
// Fragment loads via ldmatrix.m8n8.x4 (plain row-major smem tiles).
// Persistent CTAs + dynamic LPT queue; 2-D warp tiling (4 row x 2 col groups);
// Q fragments register-resident; single barrier per k-tile; diag specialization.
// B=2,H=16,L=2048,D=64. Tile: 128 q-rows, k-tiles of 128.

#define L_SEQ 2048
#define DHEAD 64
#define NBH   32
#define BM    128
#define BN    128
#define QS    72     // Q/K smem row stride in halves (144B; ldmatrix conflict-free)
#define VTS   136    // Vt smem row stride in halves (272B; ldmatrix conflict-free)
#define OS    66     // O-partial reduction row stride (floats)
#define NTILES 512
#define SMEM_MAIN ((BM * QS + 2 * BN * QS + 2 * 64 * VTS) * 2)   // 90112 B

__device__ __align__(16) __half g_Qh[NBH * L_SEQ * DHEAD];  // scaled, row-major
__device__ __align__(16) __half g_Kh[NBH * L_SEQ * DHEAD];  // row-major
__device__ __align__(16) __half g_Vth[NBH * DHEAD * L_SEQ]; // transposed [d][k]
__device__ int g_ctr;                                        // work-queue cursor

static __device__ __forceinline__ uint32_t packh2(float lo, float hi) {
    __half2 h = __floats2half2_rn(lo, hi);
    return *(uint32_t*)&h;
}
static __device__ __forceinline__ uint32_t smem_u32(const void* p) {
    uint32_t a;
    asm("{ .reg .u64 t; cvta.to.shared.u64 t, %1; cvt.u32.u64 %0, t; }" : "=r"(a) : "l"(p));
    return a;
}
static __device__ __forceinline__ void cp16(uint32_t s, const void* g) {
    asm volatile("cp.async.cg.shared.global [%0], [%1], 16;"
                 :: "r"(s), "l"(__cvta_generic_to_global(g)));
}
static __device__ __forceinline__ void cp_commit() {
    asm volatile("cp.async.commit_group;" ::: "memory");
}
static __device__ __forceinline__ void cp_wait0() {
    asm volatile("cp.async.wait_group 0;" ::: "memory");
}
static __device__ __forceinline__ void ldsm4(uint32_t& r0, uint32_t& r1,
                                             uint32_t& r2, uint32_t& r3, uint32_t a) {
    asm volatile("ldmatrix.sync.aligned.m8n8.x4.shared.b16 {%0,%1,%2,%3}, [%4];"
                 : "=r"(r0), "=r"(r1), "=r"(r2), "=r"(r3) : "r"(a));
}
static __device__ __forceinline__ void mma16(float* d,
        uint32_t a0, uint32_t a1, uint32_t a2, uint32_t a3,
        uint32_t b0, uint32_t b1) {
    asm volatile(
        "mma.sync.aligned.m16n8k16.row.col.f32.f16.f16.f32 "
        "{%0,%1,%2,%3}, {%4,%5,%6,%7}, {%8,%9}, {%0,%1,%2,%3};"
        : "+f"(d[0]), "+f"(d[1]), "+f"(d[2]), "+f"(d[3])
        : "r"(a0), "r"(a1), "r"(a2), "r"(a3), "r"(b0), "r"(b1));
}

// ---- merged prep: y=0 -> Q,K fp16 convert (plain); y=1 -> V transpose ----
__global__ void __launch_bounds__(256)
prep_all(const float* __restrict__ Q, const float* __restrict__ K,
         const float* __restrict__ V)
{
    if (blockIdx.x == 0 && blockIdx.y == 0 && threadIdx.x == 0) g_ctr = 0;

    if (blockIdx.y == 0) {
        const int g   = blockIdx.x * 256 + threadIdx.x;
        const size_t off = (size_t)(g >> 2) * DHEAD + ((g & 3) << 4);

        float4 f0 = *(const float4*)(Q + off);
        float4 f1 = *(const float4*)(Q + off + 4);
        float4 f2 = *(const float4*)(Q + off + 8);
        float4 f3 = *(const float4*)(Q + off + 12);
        uint4 a, b;
        a.x = packh2(f0.x * 0.125f, f0.y * 0.125f);
        a.y = packh2(f0.z * 0.125f, f0.w * 0.125f);
        a.z = packh2(f1.x * 0.125f, f1.y * 0.125f);
        a.w = packh2(f1.z * 0.125f, f1.w * 0.125f);
        b.x = packh2(f2.x * 0.125f, f2.y * 0.125f);
        b.y = packh2(f2.z * 0.125f, f2.w * 0.125f);
        b.z = packh2(f3.x * 0.125f, f3.y * 0.125f);
        b.w = packh2(f3.z * 0.125f, f3.w * 0.125f);
        *(uint4*)(g_Qh + off)     = a;
        *(uint4*)(g_Qh + off + 8) = b;

        f0 = *(const float4*)(K + off);
        f1 = *(const float4*)(K + off + 4);
        f2 = *(const float4*)(K + off + 8);
        f3 = *(const float4*)(K + off + 12);
        a.x = packh2(f0.x, f0.y);  a.y = packh2(f0.z, f0.w);
        a.z = packh2(f1.x, f1.y);  a.w = packh2(f1.z, f1.w);
        b.x = packh2(f2.x, f2.y);  b.y = packh2(f2.z, f2.w);
        b.z = packh2(f3.x, f3.y);  b.w = packh2(f3.z, f3.w);
        *(uint4*)(g_Kh + off)     = a;
        *(uint4*)(g_Kh + off + 8) = b;
    } else {
        __shared__ float ts[64][68];
        const int tid = threadIdx.x;
        const int kt0 = (blockIdx.x & 31) * 64;
        const int bh  = blockIdx.x >> 5;
        const float* vsrc = V + (size_t)bh * L_SEQ * DHEAD;
        __half* vdst = g_Vth + (size_t)bh * DHEAD * L_SEQ;

        #pragma unroll
        for (int i = 0; i < 4; ++i) {
            const int idx = tid + 256 * i;
            const int row = idx >> 4, c4 = (idx & 15) << 2;
            *(float4*)&ts[row][c4] =
                *(const float4*)(vsrc + (size_t)(kt0 + row) * DHEAD + c4);
        }
        __syncthreads();

        const int d  = tid >> 2;
        const int kb = (tid & 3) << 4;
        uint4 a, b;
        a.x = packh2(ts[kb + 0][d],  ts[kb + 1][d]);
        a.y = packh2(ts[kb + 2][d],  ts[kb + 3][d]);
        a.z = packh2(ts[kb + 4][d],  ts[kb + 5][d]);
        a.w = packh2(ts[kb + 6][d],  ts[kb + 7][d]);
        b.x = packh2(ts[kb + 8][d],  ts[kb + 9][d]);
        b.y = packh2(ts[kb + 10][d], ts[kb + 11][d]);
        b.z = packh2(ts[kb + 12][d], ts[kb + 13][d]);
        b.w = packh2(ts[kb + 14][d], ts[kb + 15][d]);
        __half* dst = vdst + (size_t)d * L_SEQ + kt0 + kb;
        *(uint4*)dst       = a;
        *(uint4*)(dst + 8) = b;
    }
}

// ---- one k-tile of compute for one warp (4 chunks of 16 cols) ----
// kBase/vBase: smem byte address incl. per-lane ldmatrix offset for this buffer.
template<bool DIAG>
static __device__ __forceinline__ void tile_step(
    uint32_t kBase, uint32_t vBase,
    const uint32_t (&qf)[2][4][4],
    float (&oacc)[2][8][4], float (&zr)[2][2],
    int colw, int rbase, int c)
{
    #pragma unroll
    for (int ch = 0; ch < 4; ++ch) {
        const int cb0 = colw + 16 * ch;           // chunk column base (local)
        if (DIAG && cb0 > rbase + 31) break;      // fully above all warp rows
        const bool t1 = !DIAG || (cb0 + 8 <= rbase + 31);

        // ---- MMA1: S chunk (32 rows x 16 cols); K frags via ldmatrix ----
        float sacc[2][2][4];
        #pragma unroll
        for (int mi = 0; mi < 2; ++mi)
            #pragma unroll
            for (int t = 0; t < 2; ++t)
                #pragma unroll
                for (int jj = 0; jj < 4; ++jj) sacc[mi][t][jj] = 0.0f;

        const uint32_t kCh = kBase + (uint32_t)(cb0 * QS) * 2;
        #pragma unroll
        for (int s = 0; s < 4; ++s) {
            uint32_t k0, k1, k2, k3;
            ldsm4(k0, k1, k2, k3, kCh + 32u * s);
            mma16(sacc[0][0], qf[0][s][0], qf[0][s][1], qf[0][s][2], qf[0][s][3], k0, k1);
            mma16(sacc[1][0], qf[1][s][0], qf[1][s][1], qf[1][s][2], qf[1][s][3], k0, k1);
            if (t1) {
                mma16(sacc[0][1], qf[0][s][0], qf[0][s][1], qf[0][s][2], qf[0][s][3], k2, k3);
                mma16(sacc[1][1], qf[1][s][0], qf[1][s][1], qf[1][s][2], qf[1][s][3], k2, k3);
            }
        }

        // ---- epilogue: f(s), mask, z, pack ----
        uint32_t pr[2][2][2];
        #pragma unroll
        for (int mi = 0; mi < 2; ++mi)
            #pragma unroll
            for (int t = 0; t < 2; ++t) { pr[mi][t][0] = 0u; pr[mi][t][1] = 0u; }
        #pragma unroll
        for (int mi = 0; mi < 2; ++mi) {
            const int r0 = rbase + 16 * mi + ((threadIdx.x & 31) >> 2);
            #pragma unroll
            for (int t = 0; t < 2; ++t) {
                if (DIAG && t == 1 && !t1) continue;
                const int cb = cb0 + 8 * t + 2 * c;   // local col of p0/p2
                float s0 = sacc[mi][t][0], s1 = sacc[mi][t][1];
                float s2 = sacc[mi][t][2], s3 = sacc[mi][t][3];
                float p0 = fmaf(fmaf(0.5f, s0, 1.0f), s0, 1.0f);
                float p1 = fmaf(fmaf(0.5f, s1, 1.0f), s1, 1.0f);
                float p2 = fmaf(fmaf(0.5f, s2, 1.0f), s2, 1.0f);
                float p3 = fmaf(fmaf(0.5f, s3, 1.0f), s3, 1.0f);
                if (DIAG) {
                    if (cb     > r0)     p0 = 0.0f;
                    if (cb + 1 > r0)     p1 = 0.0f;
                    if (cb     > r0 + 8) p2 = 0.0f;
                    if (cb + 1 > r0 + 8) p3 = 0.0f;
                }
                zr[mi][0] += p0 + p1;
                zr[mi][1] += p2 + p3;
                pr[mi][t][0] = packh2(p0, p1);
                pr[mi][t][1] = packh2(p2, p3);
            }
        }

        // ---- MMA2: O += P @ V ; V frags via ldmatrix; A-frag = pr in-lane ----
        const uint32_t vCh = vBase + (uint32_t)cb0 * 2;
        #pragma unroll
        for (int tp = 0; tp < 4; ++tp) {
            uint32_t v0, v1, v2, v3;
            ldsm4(v0, v1, v2, v3, vCh + (uint32_t)(32 * VTS) * tp);
            mma16(oacc[0][2 * tp],     pr[0][0][0], pr[0][0][1], pr[0][1][0], pr[0][1][1], v0, v1);
            mma16(oacc[0][2 * tp + 1], pr[0][0][0], pr[0][0][1], pr[0][1][0], pr[0][1][1], v2, v3);
            mma16(oacc[1][2 * tp],     pr[1][0][0], pr[1][0][1], pr[1][1][0], pr[1][1][1], v0, v1);
            mma16(oacc[1][2 * tp + 1], pr[1][0][0], pr[1][0][1], pr[1][1][0], pr[1][1][1], v2, v3);
        }
    }
}

// ---- main kernel: persistent CTAs over a dynamic LPT work list ----
__global__ void __launch_bounds__(256, 2)
taylor_attn_h(float* __restrict__ O)
{
    extern __shared__ __half smh[];
    __half* Qs = smh;                      // [128][72]
    __half* Kb = Qs + BM * QS;             // [2][128][72]
    __half* Vb = Kb + 2 * BN * QS;         // [2][64][136]
    int* wptr  = (int*)((char*)smh + SMEM_MAIN);
    const uint32_t sQs = smem_u32(Qs);
    const uint32_t sKb = smem_u32(Kb);
    const uint32_t sVb = smem_u32(Vb);

    const int tid  = threadIdx.x;
    const int wid  = tid >> 5;
    const int lane = tid & 31;
    const int grp  = lane >> 2;
    const int c    = lane & 3;
    const int mw   = wid & 3;              // row group (32 rows)
    const int nw   = wid >> 2;             // col group (64 cols)
    const int rbase = 32 * mw;
    const int colw  = 64 * nw;

    // per-lane ldmatrix offsets (halves)
    const int lo8 = lane & 7;
    const int selA = (lane >> 3) & 1;      // x4 matrix pair select (bit3)
    const int selB = (lane >> 4) & 1;      // x4 matrix pair select (bit4)
    // K: m0/m1 = keys lo, d lo/hi ; m2/m3 = keys+8
    const int kLane = (selB * 8 + lo8) * QS + selA * 8;
    // V: m0/m1 = d-rows lo, k lo/hi ; m2/m3 = rows+8
    const int vLane = (selB * 8 + lo8) * VTS + selA * 8;
    // Q: m0/m1 = rows lo/hi, d lo ; m2/m3 = d hi
    const int qLane = (selA * 8 + lo8) * QS + selB * 8;

    for (;;) {
        if (tid == 0) *wptr = atomicAdd(&g_ctr, 1);
        __syncthreads();
        const int widx = *wptr;
        if (widx >= NTILES) break;

        const int qt = (L_SEQ / BM) - 1 - (widx >> 5);   // LPT: big first
        const int bh = widx & 31;
        const int qbase = qt * BM;

        const __half* Qg = g_Qh + (size_t)bh * L_SEQ * DHEAD;
        const __half* Kg = g_Kh + (size_t)bh * L_SEQ * DHEAD;
        const __half* Vg = g_Vth + (size_t)bh * DHEAD * L_SEQ;

        // ---- prologue: Q tile + K/V tile 0 ----
        #pragma unroll
        for (int i = 0; i < 4; ++i) {
            const int idx = tid + 256 * i;
            const int row = idx >> 3, ch = idx & 7;
            cp16(sQs + (uint32_t)(row * QS + ch * 8) * 2,
                 Qg + (size_t)(qbase + row) * DHEAD + ch * 8);
            cp16(sKb + (uint32_t)(row * QS + ch * 8) * 2,
                 Kg + (size_t)row * DHEAD + ch * 8);
        }
        #pragma unroll
        for (int i = 0; i < 4; ++i) {
            const int idx = tid + 256 * i;
            const int row = idx >> 4, ch = idx & 15;
            cp16(sVb + (uint32_t)(row * VTS + ch * 8) * 2,
                 Vg + (size_t)row * L_SEQ + ch * 8);
        }
        cp_commit();
        cp_wait0();
        __syncthreads();

        // ---- Q fragments -> registers for the whole k-loop (ldmatrix) ----
        uint32_t qf[2][4][4];
        #pragma unroll
        for (int mi = 0; mi < 2; ++mi)
            #pragma unroll
            for (int s = 0; s < 4; ++s)
                ldsm4(qf[mi][s][0], qf[mi][s][1], qf[mi][s][2], qf[mi][s][3],
                      sQs + (uint32_t)(qLane + (rbase + 16 * mi) * QS + 16 * s) * 2);

        float oacc[2][8][4];
        #pragma unroll
        for (int mi = 0; mi < 2; ++mi)
            #pragma unroll
            for (int t = 0; t < 8; ++t)
                #pragma unroll
                for (int j = 0; j < 4; ++j) oacc[mi][t][j] = 0.0f;
        float zr[2][2] = {};

        for (int j = 0; j <= qt; ++j) {
            const int buf = j & 1;

            if (j < qt) {   // prefetch tile j+1 into the other buffer
                const int nb = buf ^ 1;
                const int kb1 = (j + 1) * BN;
                const uint32_t dK = sKb + (uint32_t)(nb * BN * QS) * 2;
                const uint32_t dV = sVb + (uint32_t)(nb * 64 * VTS) * 2;
                #pragma unroll
                for (int i = 0; i < 4; ++i) {
                    const int idx = tid + 256 * i;
                    const int rowk = idx >> 3, chk = idx & 7;
                    cp16(dK + (uint32_t)(rowk * QS + chk * 8) * 2,
                         Kg + (size_t)(kb1 + rowk) * DHEAD + chk * 8);
                    const int rowv = idx >> 4, chv = idx & 15;
                    cp16(dV + (uint32_t)(rowv * VTS + chv * 8) * 2,
                         Vg + (size_t)rowv * L_SEQ + kb1 + chv * 8);
                }
                cp_commit();
            }

            const uint32_t kBase = sKb + (uint32_t)(buf * BN * QS) * 2
                                 + (uint32_t)kLane * 2;
            const uint32_t vBase = sVb + (uint32_t)(buf * 64 * VTS) * 2
                                 + (uint32_t)vLane * 2;
            if (j == qt)
                tile_step<true >(kBase, vBase, qf, oacc, zr, colw, rbase, c);
            else
                tile_step<false>(kBase, vBase, qf, oacc, zr, colw, rbase, c);

            if (j < qt) cp_wait0();
            __syncthreads();   // buf free + next tile visible to all warps
        }

        // ---- z lane-reduce over the 4 c-lanes ----
        #pragma unroll
        for (int mi = 0; mi < 2; ++mi) {
            zr[mi][0] += __shfl_xor_sync(0xffffffffu, zr[mi][0], 1);
            zr[mi][0] += __shfl_xor_sync(0xffffffffu, zr[mi][0], 2);
            zr[mi][1] += __shfl_xor_sync(0xffffffffu, zr[mi][1], 1);
            zr[mi][1] += __shfl_xor_sync(0xffffffffu, zr[mi][1], 2);
        }

        // ---- cross-col-group reduction via smem (reuse K/V buffer space) ----
        float* Osum = (float*)(smh + BM * QS);
        float* Zsum = (float*)(smh + BM * QS + 2 * BN * QS);

        if (nw == 1) {
            float* base = Osum + mw * 32 * OS;
            #pragma unroll
            for (int mi = 0; mi < 2; ++mi) {
                const int r0 = 16 * mi + grp;
                #pragma unroll
                for (int tn = 0; tn < 8; ++tn) {
                    *(float2*)(base + r0 * OS + 8 * tn + 2 * c) =
                        make_float2(oacc[mi][tn][0], oacc[mi][tn][1]);
                    *(float2*)(base + (r0 + 8) * OS + 8 * tn + 2 * c) =
                        make_float2(oacc[mi][tn][2], oacc[mi][tn][3]);
                }
                if (c == 0) {
                    Zsum[rbase + 16 * mi + grp]     = zr[mi][0];
                    Zsum[rbase + 16 * mi + grp + 8] = zr[mi][1];
                }
            }
        }
        __syncthreads();

        if (nw == 0) {
            float* base = Osum + mw * 32 * OS;
            #pragma unroll
            for (int mi = 0; mi < 2; ++mi) {
                const int r0 = 16 * mi + grp;
                const float z0 = zr[mi][0] + Zsum[rbase + r0];
                const float z1 = zr[mi][1] + Zsum[rbase + r0 + 8];
                const float inv0 = 1.0f / (z0 + 1e-6f);
                const float inv1 = 1.0f / (z1 + 1e-6f);
                float* ob0 = O + (size_t)bh * L_SEQ * DHEAD
                           + (size_t)(qbase + rbase + r0) * DHEAD + 2 * c;
                float* ob1 = ob0 + 8 * DHEAD;
                #pragma unroll
                for (int tn = 0; tn < 8; ++tn) {
                    const float2 s0 = *(const float2*)(base + r0 * OS + 8 * tn + 2 * c);
                    const float2 s1 = *(const float2*)(base + (r0 + 8) * OS + 8 * tn + 2 * c);
                    float2 w0, w1;
                    w0.x = (oacc[mi][tn][0] + s0.x) * inv0;
                    w0.y = (oacc[mi][tn][1] + s0.y) * inv0;
                    w1.x = (oacc[mi][tn][2] + s1.x) * inv1;
                    w1.y = (oacc[mi][tn][3] + s1.y) * inv1;
                    *(float2*)(ob0 + 8 * tn) = w0;
                    *(float2*)(ob1 + 8 * tn) = w1;
                }
            }
        }
        __syncthreads();   // Osum readers done before next tile's prologue
    }
}

extern "C" void kernel_launch(void* const* d_in, const int* in_sizes, int n_in,
                              void* d_out, int out_size) {
    (void)in_sizes; (void)n_in; (void)out_size;
    const float* q = (const float*)d_in[0];
    const float* k = (const float*)d_in[1];
    const float* v = (const float*)d_in[2];
    float* o = (float*)d_out;

    const int smem_bytes = SMEM_MAIN + 16;
    static bool configured = false;
    if (!configured) {
        cudaFuncSetAttribute(taylor_attn_h,
                             cudaFuncAttributeMaxDynamicSharedMemorySize, smem_bytes);
        configured = true;
    }

    prep_all<<<dim3(1024, 2), 256>>>(q, k, v);

    taylor_attn_h<<<304, 256, smem_bytes>>>(o);   // persistent: 2 CTAs x 152 SMs
}